// round 7
// baseline (speedup 1.0000x reference)
#include <cuda_runtime.h>
#include <math.h>

// Problem dims
#define NL  2
#define NB  2
#define T_  2048
#define C_  512
#define H_  8
#define FF_ 1024
#define HS_ 64
#define EPS_ 1.1920929e-07f

#define BT_  (NB * T_)        // 4096 rows
#define BTC_ (NB * T_ * C_)   // 2097152
#define BH_  (NB * H_)        // 16

// ---------------- scratch ----------------
__device__ float g_xnorm[BTC_];
__device__ float g_hnorm[BTC_];
__device__ float g_q[BTC_];      // [B,H,T,HS]
__device__ float g_k[BTC_];
__device__ float g_v[BTC_];
__device__ float g_attn[BTC_];   // [B,T,C]
__device__ float g_ff[NB * T_ * FF_];

// ---------------- cp.async helpers ----------------
__device__ __forceinline__ unsigned sm_u32(const void* p) {
    return (unsigned)__cvta_generic_to_shared(p);
}
__device__ __forceinline__ void cp16(void* dst_smem, const void* src) {
    asm volatile("cp.async.cg.shared.global [%0], [%1], 16;"
                 :: "r"(sm_u32(dst_smem)), "l"(src));
}
#define CP_COMMIT() asm volatile("cp.async.commit_group;")
#define CP_WAIT(n)  asm volatile("cp.async.wait_group %0;" :: "n"(n))

// ---------------- helpers ----------------
__global__ void copy_k(float4* __restrict__ dst, const float4* __restrict__ src, int n4) {
    int i = blockIdx.x * blockDim.x + threadIdx.x;
    if (i < n4) dst[i] = src[i];
}

__global__ __launch_bounds__(256) void rmsnorm_k(
    const float* __restrict__ x, const float* __restrict__ g, float* __restrict__ out)
{
    long row = blockIdx.x;
    const float* xr = x + row * C_;
    float* orow = out + row * C_;
    int tid = threadIdx.x;
    float v0 = xr[tid];
    float v1 = xr[tid + 256];
    float ss = v0 * v0 + v1 * v1;

    __shared__ float red[8];
    #pragma unroll
    for (int o = 16; o; o >>= 1) ss += __shfl_xor_sync(0xffffffffu, ss, o);
    if ((tid & 31) == 0) red[tid >> 5] = ss;
    __syncthreads();
    if (tid == 0) {
        float s = 0.f;
        #pragma unroll
        for (int w = 0; w < 8; w++) s += red[w];
        red[0] = rsqrtf(s * (1.0f / C_) + EPS_);
    }
    __syncthreads();
    float r = red[0];
    orow[tid]       = v0 * r * g[tid];
    orow[tid + 256] = v1 * r * g[tid + 256];
}

// ---------------- tf32 mma (raw fp32 bits -> tf32 truncation) ----------------
__device__ __forceinline__ void mma_tf32(float* d, const unsigned* a, const unsigned* b) {
    asm volatile(
        "mma.sync.aligned.m16n8k8.row.col.f32.tf32.tf32.f32 "
        "{%0,%1,%2,%3}, {%4,%5,%6,%7}, {%8,%9}, {%0,%1,%2,%3};"
        : "+f"(d[0]), "+f"(d[1]), "+f"(d[2]), "+f"(d[3])
        : "r"(a[0]), "r"(a[1]), "r"(a[2]), "r"(a[3]), "r"(b[0]), "r"(b[1]));
}
__device__ __forceinline__ unsigned fbits(float x) { return __float_as_uint(x); }

// ---------------- dense GEMM: 128x128 tile, BK=16, cp.async 2-stage ----------------
#define ASTR 20
#define BSTR 136
__global__ __launch_bounds__(256) void gemm128(
    int K,
    const float* __restrict__ A, int lda, long Ab,
    const float* __restrict__ B0, const float* __restrict__ B1, const float* __restrict__ B2,
    int ldb, long Bh, int headN,
    const float* __restrict__ bias,
    float* __restrict__ C0, float* __restrict__ C1, float* __restrict__ C2,
    int ldc, long Cb, long Ch, int headC,
    int accumulate, int gelu_act, int nColBlk)
{
    __shared__ float As[2][128 * ASTR];
    __shared__ float Bs[2][16 * BSTR];

    int sel  = blockIdx.x / nColBlk;
    int colb = blockIdx.x - sel * nColBlk;
    const float* B = (sel == 0) ? B0 : (sel == 1) ? B1 : B2;
    float* Cp      = (sel == 0) ? C0 : (sel == 1) ? C1 : C2;

    int z = blockIdx.z;
    A  += (long)z * Ab;
    Cp += (long)z * Cb;

    int row0 = blockIdx.y * 128;
    int col0 = colb * 128;

    int tid = threadIdx.x;
    int lane = tid & 31, w = tid >> 5;
    int g = lane >> 2, t4 = lane & 3;
    int wm = w & 1, wn = w >> 1;           // 2x4 warp grid: 64 rows x 32 cols

    float acc[4][4][4];
    #pragma unroll
    for (int i = 0; i < 4; i++)
        #pragma unroll
        for (int j = 0; j < 4; j++)
            #pragma unroll
            for (int q = 0; q < 4; q++) acc[i][j][q] = 0.f;

    const float* Abase = A + (long)row0 * lda;

    auto issue = [&](int st, int k0) {
        #pragma unroll
        for (int j = 0; j < 2; j++) {
            int c   = tid * 2 + j;
            int row = c >> 2;
            int kc  = (c & 3) * 4;
            cp16(&As[st][row * ASTR + kc], Abase + (long)row * lda + k0 + kc);
        }
        #pragma unroll
        for (int j = 0; j < 2; j++) {
            int c  = tid * 2 + j;
            int kk = c >> 5;
            int n4 = (c & 31) * 4;
            const float* gp;
            if (headN) {
                int gc = col0 + n4;
                gp = &B[(long)(gc >> 6) * Bh + (long)(k0 + kk) * HS_ + (gc & 63)];
            } else {
                gp = &B[(long)(k0 + kk) * ldb + col0 + n4];
            }
            cp16(&Bs[st][kk * BSTR + n4], gp);
        }
    };

    int nK = K >> 4;
    issue(0, 0);
    CP_COMMIT();

    for (int kt = 0; kt < nK; kt++) {
        int s = kt & 1;
        CP_WAIT(0);
        __syncthreads();
        if (kt + 1 < nK) {
            issue(s ^ 1, (kt + 1) * 16);
            CP_COMMIT();
        }

        #pragma unroll
        for (int kc = 0; kc < 16; kc += 8) {
            unsigned afr[4][4], bfr[4][2];
            #pragma unroll
            for (int mi = 0; mi < 4; mi++) {
                int m = wm * 64 + mi * 16 + g;
                afr[mi][0] = fbits(As[s][m * ASTR + kc + t4]);
                afr[mi][1] = fbits(As[s][(m + 8) * ASTR + kc + t4]);
                afr[mi][2] = fbits(As[s][m * ASTR + kc + t4 + 4]);
                afr[mi][3] = fbits(As[s][(m + 8) * ASTR + kc + t4 + 4]);
            }
            #pragma unroll
            for (int ni = 0; ni < 4; ni++) {
                int n = wn * 32 + ni * 8 + g;
                bfr[ni][0] = fbits(Bs[s][(kc + t4) * BSTR + n]);
                bfr[ni][1] = fbits(Bs[s][(kc + t4 + 4) * BSTR + n]);
            }
            #pragma unroll
            for (int mi = 0; mi < 4; mi++)
                #pragma unroll
                for (int ni = 0; ni < 4; ni++)
                    mma_tf32(acc[mi][ni], afr[mi], bfr[ni]);
        }
    }

    // epilogue
    #pragma unroll
    for (int mi = 0; mi < 4; mi++) {
        #pragma unroll
        for (int ni = 0; ni < 4; ni++) {
            int r0 = row0 + wm * 64 + mi * 16 + g;
            int c  = col0 + wn * 32 + ni * 8 + t4 * 2;
            #pragma unroll
            for (int half = 0; half < 2; half++) {
                int rr = r0 + half * 8;
                float* crow;
                if (headC) crow = &Cp[(long)(c >> 6) * Ch + (long)rr * HS_ + (c & 63)];
                else       crow = &Cp[(long)rr * ldc + c];
                #pragma unroll
                for (int jj = 0; jj < 2; jj++) {
                    float vv = acc[mi][ni][half * 2 + jj];
                    if (bias) vv += bias[c + jj];
                    if (gelu_act) vv = 0.5f * vv * (1.0f + erff(vv * 0.70710678118654752f));
                    if (accumulate) crow[jj] += vv;
                    else            crow[jj]  = vv;
                }
            }
        }
    }
}

// ---------------- fused flash attention ----------------
// P stays in registers (fragment permute via shuffles). 2-stage cp.async KV.
// Dyn smem: Ks[2][64][68] + Vs[2][64][72] = 71680 B -> 2 CTAs/SM.
#define KS_W 68
#define VS_W 72
#define FLASH_SMEM ((2*64*KS_W + 2*64*VS_W) * 4)

__global__ __launch_bounds__(256, 2) void flash_k(
    const float* __restrict__ Qg,
    const float* __restrict__ Kg,
    const float* __restrict__ Vg,
    float* __restrict__ Out,
    int causal)
{
    extern __shared__ float sh[];
    float* KsB = sh;                       // [2][64*KS_W]
    float* VsB = sh + 2 * 64 * KS_W;       // [2][64*VS_W]

    int bh = blockIdx.y;
    int b = bh >> 3, h = bh & 7;
    int q0 = blockIdx.x * 128;
    long base = (long)bh * T_ * HS_;
    const float* Qb = Qg + base;
    const float* Kb = Kg + base;
    const float* Vb = Vg + base;

    int tid = threadIdx.x;
    int lane = tid & 31, w = tid >> 5;
    int g = lane >> 2, t4 = lane & 3;
    int wr = w * 16;

    auto loadKV = [&](int st, int s0) {
        #pragma unroll
        for (int j = 0; j < 4; j++) {
            int c = tid + j * 256;
            int row = c >> 4;
            int cc = (c & 15) * 4;
            cp16(&KsB[st * 64 * KS_W + row * KS_W + cc], Kb + (long)(s0 + row) * HS_ + cc);
            cp16(&VsB[st * 64 * VS_W + row * VS_W + cc], Vb + (long)(s0 + row) * HS_ + cc);
        }
    };

    // Q fragments (raw fp32 bits), held for the whole block
    unsigned Qa[8][4];
    {
        const float* q0p = Qb + (long)(q0 + wr + g) * HS_;
        const float* q1p = Qb + (long)(q0 + wr + g + 8) * HS_;
        #pragma unroll
        for (int kk = 0; kk < 8; kk++) {
            Qa[kk][0] = fbits(q0p[kk * 8 + t4]);
            Qa[kk][1] = fbits(q1p[kk * 8 + t4]);
            Qa[kk][2] = fbits(q0p[kk * 8 + t4 + 4]);
            Qa[kk][3] = fbits(q1p[kk * 8 + t4 + 4]);
        }
    }

    float Oacc[8][4];
    #pragma unroll
    for (int i = 0; i < 8; i++)
        #pragma unroll
        for (int j = 0; j < 4; j++) Oacc[i][j] = 0.f;
    float m0 = -1e30f, m1 = -1e30f, l0 = 0.f, l1 = 0.f;

    int nT = causal ? (q0 / 64 + 2) : (T_ / 64);

    loadKV(0, 0);
    CP_COMMIT();

    int src0 = (lane & ~3) | (t4 >> 1);
    int src1 = src0 + 2;
    bool odd = t4 & 1;

    for (int it = 0; it < nT; it++) {
        int s = it & 1;
        int s0 = it * 64;
        CP_WAIT(0);
        __syncthreads();
        if (it + 1 < nT) {
            loadKV(s ^ 1, (it + 1) * 64);
            CP_COMMIT();
        }

        const float* Ks = KsB + s * 64 * KS_W;
        const float* Vs = VsB + s * 64 * VS_W;

        // S = (Q K^T) * 0.125
        float S[8][4];
        #pragma unroll
        for (int nf = 0; nf < 8; nf++)
            #pragma unroll
            for (int j = 0; j < 4; j++) S[nf][j] = 0.f;

        #pragma unroll
        for (int kk = 0; kk < 8; kk++) {
            #pragma unroll
            for (int nf = 0; nf < 8; nf++) {
                unsigned b2[2];
                b2[0] = fbits(Ks[(nf * 8 + g) * KS_W + kk * 8 + t4]);
                b2[1] = fbits(Ks[(nf * 8 + g) * KS_W + kk * 8 + t4 + 4]);
                mma_tf32(S[nf], Qa[kk], b2);
            }
        }
        #pragma unroll
        for (int nf = 0; nf < 8; nf++)
            #pragma unroll
            for (int j = 0; j < 4; j++) S[nf][j] *= 0.125f;

        // causal mask (diagonal tiles only)
        if (causal && (s0 + 63 > q0 + wr)) {
            int r0g = q0 + wr + g;
            #pragma unroll
            for (int nf = 0; nf < 8; nf++) {
                int cbase = s0 + nf * 8 + 2 * t4;
                if (cbase     > r0g)     S[nf][0] = -1e30f;
                if (cbase + 1 > r0g)     S[nf][1] = -1e30f;
                if (cbase     > r0g + 8) S[nf][2] = -1e30f;
                if (cbase + 1 > r0g + 8) S[nf][3] = -1e30f;
            }
        }

        // row max (reduce over t4 quad)
        float tm0 = -1e30f, tm1 = -1e30f;
        #pragma unroll
        for (int nf = 0; nf < 8; nf++) {
            tm0 = fmaxf(tm0, fmaxf(S[nf][0], S[nf][1]));
            tm1 = fmaxf(tm1, fmaxf(S[nf][2], S[nf][3]));
        }
        tm0 = fmaxf(tm0, __shfl_xor_sync(0xffffffffu, tm0, 1));
        tm0 = fmaxf(tm0, __shfl_xor_sync(0xffffffffu, tm0, 2));
        tm1 = fmaxf(tm1, __shfl_xor_sync(0xffffffffu, tm1, 1));
        tm1 = fmaxf(tm1, __shfl_xor_sync(0xffffffffu, tm1, 2));

        float nm0 = fmaxf(m0, tm0), nm1 = fmaxf(m1, tm1);
        float f0 = __expf(m0 - nm0), f1 = __expf(m1 - nm1);

        // exponentiate in place, accumulate row sums
        float rs0 = 0.f, rs1 = 0.f;
        #pragma unroll
        for (int nf = 0; nf < 8; nf++) {
            S[nf][0] = __expf(S[nf][0] - nm0);
            S[nf][1] = __expf(S[nf][1] - nm0);
            S[nf][2] = __expf(S[nf][2] - nm1);
            S[nf][3] = __expf(S[nf][3] - nm1);
            rs0 += S[nf][0] + S[nf][1];
            rs1 += S[nf][2] + S[nf][3];
        }
        rs0 += __shfl_xor_sync(0xffffffffu, rs0, 1);
        rs0 += __shfl_xor_sync(0xffffffffu, rs0, 2);
        rs1 += __shfl_xor_sync(0xffffffffu, rs1, 1);
        rs1 += __shfl_xor_sync(0xffffffffu, rs1, 2);

        l0 = l0 * f0 + rs0;
        l1 = l1 * f1 + rs1;
        m0 = nm0; m1 = nm1;

        #pragma unroll
        for (int nf = 0; nf < 8; nf++) {
            Oacc[nf][0] *= f0; Oacc[nf][1] *= f0;
            Oacc[nf][2] *= f1; Oacc[nf][3] *= f1;
        }

        // O += P V  (P fragments via in-warp shuffle permute)
        #pragma unroll
        for (int kk = 0; kk < 8; kk++) {
            float e0a = __shfl_sync(0xffffffffu, S[kk][0], src0);
            float e1a = __shfl_sync(0xffffffffu, S[kk][1], src0);
            float e2a = __shfl_sync(0xffffffffu, S[kk][2], src0);
            float e3a = __shfl_sync(0xffffffffu, S[kk][3], src0);
            float e0b = __shfl_sync(0xffffffffu, S[kk][0], src1);
            float e1b = __shfl_sync(0xffffffffu, S[kk][1], src1);
            float e2b = __shfl_sync(0xffffffffu, S[kk][2], src1);
            float e3b = __shfl_sync(0xffffffffu, S[kk][3], src1);
            unsigned a4[4];
            a4[0] = fbits(odd ? e1a : e0a);   // row g,   col kk*8+t4
            a4[1] = fbits(odd ? e3a : e2a);   // row g+8, col kk*8+t4
            a4[2] = fbits(odd ? e1b : e0b);   // row g,   col kk*8+t4+4
            a4[3] = fbits(odd ? e3b : e2b);   // row g+8, col kk*8+t4+4
            #pragma unroll
            for (int nf = 0; nf < 8; nf++) {
                unsigned b2[2];
                b2[0] = fbits(Vs[(kk * 8 + t4) * VS_W + nf * 8 + g]);
                b2[1] = fbits(Vs[(kk * 8 + t4 + 4) * VS_W + nf * 8 + g]);
                mma_tf32(Oacc[nf], a4, b2);
            }
        }
    }

    // epilogue: normalize and write [B,T,C]
    float inv0 = 1.f / l0, inv1 = 1.f / l1;
    float* o0 = Out + ((long)b * T_ + q0 + wr + g) * C_ + h * HS_;
    float* o1 = Out + ((long)b * T_ + q0 + wr + g + 8) * C_ + h * HS_;
    #pragma unroll
    for (int nf = 0; nf < 8; nf++) {
        int c = nf * 8 + 2 * t4;
        float2 v0 = {Oacc[nf][0] * inv0, Oacc[nf][1] * inv0};
        float2 v1 = {Oacc[nf][2] * inv1, Oacc[nf][3] * inv1};
        *reinterpret_cast<float2*>(o0 + c) = v0;
        *reinterpret_cast<float2*>(o1 + c) = v1;
    }
}

// ---------------- orchestration ----------------
extern "C" void kernel_launch(void* const* d_in, const int* in_sizes, int n_in,
                              void* d_out, int out_size)
{
    const float* hidden = (const float*)d_in[0];
    const float* target = (const float*)d_in[1];
    const float* Wq_s = (const float*)d_in[2];
    const float* Wk_s = (const float*)d_in[3];
    const float* Wv_s = (const float*)d_in[4];
    const float* Wo_s = (const float*)d_in[5];
    const float* bo_s = (const float*)d_in[6];
    const float* Wq_x = (const float*)d_in[7];
    const float* Wk_x = (const float*)d_in[8];
    const float* Wv_x = (const float*)d_in[9];
    const float* Wo_x = (const float*)d_in[10];
    const float* bo_x = (const float*)d_in[11];
    const float* W1 = (const float*)d_in[12];
    const float* b1 = (const float*)d_in[13];
    const float* W2 = (const float*)d_in[14];
    const float* b2 = (const float*)d_in[15];
    const float* g1 = (const float*)d_in[16];
    const float* g2 = (const float*)d_in[17];
    const float* g3 = (const float*)d_in[18];
    const float* g4 = (const float*)d_in[19];

    float* t = (float*)d_out;

    float *xnorm, *hnorm, *q, *k, *v, *attn, *ff;
    cudaGetSymbolAddress((void**)&xnorm, g_xnorm);
    cudaGetSymbolAddress((void**)&hnorm, g_hnorm);
    cudaGetSymbolAddress((void**)&q, g_q);
    cudaGetSymbolAddress((void**)&k, g_k);
    cudaGetSymbolAddress((void**)&v, g_v);
    cudaGetSymbolAddress((void**)&attn, g_attn);
    cudaGetSymbolAddress((void**)&ff, g_ff);

    cudaFuncSetAttribute(flash_k, cudaFuncAttributeMaxDynamicSharedMemorySize, FLASH_SMEM);

    copy_k<<<(BTC_ / 4 + 255) / 256, 256>>>((float4*)t, (const float4*)target, BTC_ / 4);

    const long HCHS = (long)H_ * C_ * HS_;   // per-layer weight stride
    const long CHS  = (long)C_ * HS_;        // per-head weight stride
    const long BHT  = (long)H_ * T_ * HS_;   // per-b stride of q/k/v

    dim3 gQKV(12, T_ / 128, NB);             // 3 projections x 4 col-blocks, z=b
    dim3 gO(C_ / 128, BT_ / 128, 1);
    dim3 gF1(FF_ / 128, BT_ / 128, 1);
    dim3 gF2(C_ / 128, BT_ / 128, 1);
    dim3 gFl(T_ / 128, BH_, 1);

    for (int l = 0; l < NL; l++) {
        // ======== masked self-attention ========
        rmsnorm_k<<<BT_, 256>>>(t, g1 + (long)l * C_, xnorm);

        gemm128<<<gQKV, 256>>>(C_,
            xnorm, C_, (long)T_ * C_,
            Wq_s + l * HCHS, Wk_s + l * HCHS, Wv_s + l * HCHS, 0, CHS, 1,
            nullptr,
            q, k, v, 0, BHT, (long)T_ * HS_, 1,
            0, 0, 4);

        flash_k<<<gFl, 256, FLASH_SMEM>>>(q, k, v, attn, 1);

        gemm128<<<gO, 256>>>(C_,
            attn, C_, 0,
            Wo_s + (long)l * C_ * C_, Wo_s + (long)l * C_ * C_, Wo_s + (long)l * C_ * C_,
            C_, 0, 0,
            bo_s + (long)l * C_,
            t, t, t, C_, 0, 0, 0,
            1, 0, C_ / 128);

        // ======== cross-attention ========
        rmsnorm_k<<<BT_, 256>>>(hidden, g2 + (long)l * C_, hnorm);
        rmsnorm_k<<<BT_, 256>>>(t, g3 + (long)l * C_, xnorm);

        // Q from xnorm
        gemm128<<<dim3(4, T_ / 128, NB), 256>>>(C_,
            xnorm, C_, (long)T_ * C_,
            Wq_x + l * HCHS, Wq_x + l * HCHS, Wq_x + l * HCHS, 0, CHS, 1,
            nullptr,
            q, q, q, 0, BHT, (long)T_ * HS_, 1,
            0, 0, 4);
        // K,V from hnorm (fused pair)
        gemm128<<<dim3(8, T_ / 128, NB), 256>>>(C_,
            hnorm, C_, (long)T_ * C_,
            Wk_x + l * HCHS, Wv_x + l * HCHS, Wv_x + l * HCHS, 0, CHS, 1,
            nullptr,
            k, v, v, 0, BHT, (long)T_ * HS_, 1,
            0, 0, 4);

        flash_k<<<gFl, 256, FLASH_SMEM>>>(q, k, v, attn, 0);

        gemm128<<<gO, 256>>>(C_,
            attn, C_, 0,
            Wo_x + (long)l * C_ * C_, Wo_x + (long)l * C_ * C_, Wo_x + (long)l * C_ * C_,
            C_, 0, 0,
            bo_x + (long)l * C_,
            t, t, t, C_, 0, 0, 0,
            1, 0, C_ / 128);

        // ======== GELU FFN ========
        rmsnorm_k<<<BT_, 256>>>(t, g4 + (long)l * C_, xnorm);

        gemm128<<<gF1, 256>>>(C_,
            xnorm, C_, 0,
            W1 + (long)l * C_ * FF_, W1 + (long)l * C_ * FF_, W1 + (long)l * C_ * FF_,
            FF_, 0, 0,
            b1 + (long)l * FF_,
            ff, ff, ff, FF_, 0, 0, 0,
            0, 1, FF_ / 128);

        gemm128<<<gF2, 256>>>(FF_,
            ff, FF_, 0,
            W2 + (long)l * FF_ * C_, W2 + (long)l * FF_ * C_, W2 + (long)l * FF_ * C_,
            C_, 0, 0,
            b2 + (long)l * C_,
            t, t, t, C_, 0, 0, 0,
            1, 0, C_ / 128);
    }
}

// round 8
// speedup vs baseline: 1.3231x; 1.3231x over previous
#include <cuda_runtime.h>
#include <cuda_bf16.h>
#include <math.h>

// Problem dims
#define NL  2
#define NB  2
#define T_  2048
#define C_  512
#define H_  8
#define FF_ 1024
#define HS_ 64
#define EPS_ 1.1920929e-07f

#define BT_  (NB * T_)        // 4096 rows
#define BTC_ (NB * T_ * C_)   // 2097152
#define BH_  (NB * H_)        // 16

// ---------------- scratch ----------------
__device__ float g_xnorm[BTC_];
__device__ float g_hnorm[BTC_];
__device__ __nv_bfloat16 g_q[BTC_];   // [B,H,T,HS] bf16
__device__ __nv_bfloat16 g_k[BTC_];
__device__ __nv_bfloat16 g_v[BTC_];
__device__ float g_attn[BTC_];        // [B,T,C]
__device__ float g_ff[NB * T_ * FF_];

// ---------------- cp.async helpers ----------------
__device__ __forceinline__ unsigned sm_u32(const void* p) {
    return (unsigned)__cvta_generic_to_shared(p);
}
__device__ __forceinline__ void cp16(void* dst_smem, const void* src) {
    asm volatile("cp.async.cg.shared.global [%0], [%1], 16;"
                 :: "r"(sm_u32(dst_smem)), "l"(src));
}
#define CP_COMMIT() asm volatile("cp.async.commit_group;")
#define CP_WAIT(n)  asm volatile("cp.async.wait_group %0;" :: "n"(n))

// ---------------- helpers ----------------
__global__ void copy_k(float4* __restrict__ dst, const float4* __restrict__ src, int n4) {
    int i = blockIdx.x * blockDim.x + threadIdx.x;
    if (i < n4) dst[i] = src[i];
}

__global__ __launch_bounds__(256) void rmsnorm_k(
    const float* __restrict__ x, const float* __restrict__ g, float* __restrict__ out)
{
    long row = blockIdx.x;
    const float* xr = x + row * C_;
    float* orow = out + row * C_;
    int tid = threadIdx.x;
    float v0 = xr[tid];
    float v1 = xr[tid + 256];
    float ss = v0 * v0 + v1 * v1;

    __shared__ float red[8];
    #pragma unroll
    for (int o = 16; o; o >>= 1) ss += __shfl_xor_sync(0xffffffffu, ss, o);
    if ((tid & 31) == 0) red[tid >> 5] = ss;
    __syncthreads();
    if (tid == 0) {
        float s = 0.f;
        #pragma unroll
        for (int w = 0; w < 8; w++) s += red[w];
        red[0] = rsqrtf(s * (1.0f / C_) + EPS_);
    }
    __syncthreads();
    float r = red[0];
    orow[tid]       = v0 * r * g[tid];
    orow[tid + 256] = v1 * r * g[tid + 256];
}

// ---------------- mma helpers ----------------
__device__ __forceinline__ void mma_tf32(float* d, const unsigned* a, const unsigned* b) {
    asm volatile(
        "mma.sync.aligned.m16n8k8.row.col.f32.tf32.tf32.f32 "
        "{%0,%1,%2,%3}, {%4,%5,%6,%7}, {%8,%9}, {%0,%1,%2,%3};"
        : "+f"(d[0]), "+f"(d[1]), "+f"(d[2]), "+f"(d[3])
        : "r"(a[0]), "r"(a[1]), "r"(a[2]), "r"(a[3]), "r"(b[0]), "r"(b[1]));
}
__device__ __forceinline__ void mma_bf16(float* d, const unsigned* a, unsigned b0, unsigned b1) {
    asm volatile(
        "mma.sync.aligned.m16n8k16.row.col.f32.bf16.bf16.f32 "
        "{%0,%1,%2,%3}, {%4,%5,%6,%7}, {%8,%9}, {%0,%1,%2,%3};"
        : "+f"(d[0]), "+f"(d[1]), "+f"(d[2]), "+f"(d[3])
        : "r"(a[0]), "r"(a[1]), "r"(a[2]), "r"(a[3]), "r"(b0), "r"(b1));
}
__device__ __forceinline__ unsigned fbits(float x) { return __float_as_uint(x); }
// pack {lo, hi} floats -> bf16x2 (rn)
__device__ __forceinline__ unsigned packbf(float lo, float hi) {
    unsigned d;
    asm("cvt.rn.bf16x2.f32 %0, %1, %2;" : "=r"(d) : "f"(hi), "f"(lo));
    return d;
}

// ---------------- dense GEMM: 128x128 tile, BK=16, cp.async 2-stage ----------------
#define ASTR 20
#define BSTR 136
__global__ __launch_bounds__(256) void gemm128(
    int K,
    const float* __restrict__ A, int lda, long Ab,
    const float* __restrict__ B0, const float* __restrict__ B1, const float* __restrict__ B2,
    int ldb, long Bh, int headN,
    const float* __restrict__ bias,
    float* __restrict__ C0, float* __restrict__ C1, float* __restrict__ C2,
    int ldc, long Cb, long Ch, int headC,
    int accumulate, int gelu_act, int nColBlk, int out_bf16)
{
    __shared__ float As[2][128 * ASTR];
    __shared__ float Bs[2][16 * BSTR];

    int sel  = blockIdx.x / nColBlk;
    int colb = blockIdx.x - sel * nColBlk;
    const float* B = (sel == 0) ? B0 : (sel == 1) ? B1 : B2;
    float* Cbase   = (sel == 0) ? C0 : (sel == 1) ? C1 : C2;

    int z = blockIdx.z;
    A += (long)z * Ab;

    int row0 = blockIdx.y * 128;
    int col0 = colb * 128;

    int tid = threadIdx.x;
    int lane = tid & 31, w = tid >> 5;
    int g = lane >> 2, t4 = lane & 3;
    int wm = w & 1, wn = w >> 1;           // 2x4 warp grid: 64 rows x 32 cols

    float acc[4][4][4];
    #pragma unroll
    for (int i = 0; i < 4; i++)
        #pragma unroll
        for (int j = 0; j < 4; j++)
            #pragma unroll
            for (int q = 0; q < 4; q++) acc[i][j][q] = 0.f;

    const float* Abase = A + (long)row0 * lda;

    auto issue = [&](int st, int k0) {
        #pragma unroll
        for (int j = 0; j < 2; j++) {
            int c   = tid * 2 + j;
            int row = c >> 2;
            int kc  = (c & 3) * 4;
            cp16(&As[st][row * ASTR + kc], Abase + (long)row * lda + k0 + kc);
        }
        #pragma unroll
        for (int j = 0; j < 2; j++) {
            int c  = tid * 2 + j;
            int kk = c >> 5;
            int n4 = (c & 31) * 4;
            const float* gp;
            if (headN) {
                int gc = col0 + n4;
                gp = &B[(long)(gc >> 6) * Bh + (long)(k0 + kk) * HS_ + (gc & 63)];
            } else {
                gp = &B[(long)(k0 + kk) * ldb + col0 + n4];
            }
            cp16(&Bs[st][kk * BSTR + n4], gp);
        }
    };

    int nK = K >> 4;
    issue(0, 0);
    CP_COMMIT();

    for (int kt = 0; kt < nK; kt++) {
        int s = kt & 1;
        CP_WAIT(0);
        __syncthreads();
        if (kt + 1 < nK) {
            issue(s ^ 1, (kt + 1) * 16);
            CP_COMMIT();
        }

        #pragma unroll
        for (int kc = 0; kc < 16; kc += 8) {
            unsigned afr[4][4], bfr[4][2];
            #pragma unroll
            for (int mi = 0; mi < 4; mi++) {
                int m = wm * 64 + mi * 16 + g;
                afr[mi][0] = fbits(As[s][m * ASTR + kc + t4]);
                afr[mi][1] = fbits(As[s][(m + 8) * ASTR + kc + t4]);
                afr[mi][2] = fbits(As[s][m * ASTR + kc + t4 + 4]);
                afr[mi][3] = fbits(As[s][(m + 8) * ASTR + kc + t4 + 4]);
            }
            #pragma unroll
            for (int ni = 0; ni < 4; ni++) {
                int n = wn * 32 + ni * 8 + g;
                bfr[ni][0] = fbits(Bs[s][(kc + t4) * BSTR + n]);
                bfr[ni][1] = fbits(Bs[s][(kc + t4 + 4) * BSTR + n]);
            }
            #pragma unroll
            for (int mi = 0; mi < 4; mi++)
                #pragma unroll
                for (int ni = 0; ni < 4; ni++)
                    mma_tf32(acc[mi][ni], afr[mi], bfr[ni]);
        }
    }

    // epilogue
    float* CpF = Cbase + (long)z * Cb;
    __nv_bfloat16* CpB = ((__nv_bfloat16*)Cbase) + (long)z * Cb;

    #pragma unroll
    for (int mi = 0; mi < 4; mi++) {
        #pragma unroll
        for (int ni = 0; ni < 4; ni++) {
            int r0 = row0 + wm * 64 + mi * 16 + g;
            int c  = col0 + wn * 32 + ni * 8 + t4 * 2;
            #pragma unroll
            for (int half = 0; half < 2; half++) {
                int rr = r0 + half * 8;
                float v0 = acc[mi][ni][half * 2 + 0];
                float v1 = acc[mi][ni][half * 2 + 1];
                if (bias) { v0 += bias[c]; v1 += bias[c + 1]; }
                if (gelu_act) {
                    v0 = 0.5f * v0 * (1.0f + erff(v0 * 0.70710678118654752f));
                    v1 = 0.5f * v1 * (1.0f + erff(v1 * 0.70710678118654752f));
                }
                if (out_bf16) {
                    // headC layout, bf16, no bias/accum (QKV path)
                    long idx = (long)(c >> 6) * Ch + (long)rr * HS_ + (c & 63);
                    *reinterpret_cast<unsigned*>(&CpB[idx]) = packbf(v0, v1);
                } else {
                    float* crow;
                    if (headC) crow = &CpF[(long)(c >> 6) * Ch + (long)rr * HS_ + (c & 63)];
                    else       crow = &CpF[(long)rr * ldc + c];
                    if (accumulate) { crow[0] += v0; crow[1] += v1; }
                    else            { crow[0]  = v0; crow[1]  = v1; }
                }
            }
        }
    }
}

// ---------------- fused flash attention (bf16 mma m16n8k16, online softmax) ----------------
// Q,K,V: [B,H,T,HS] bf16.  Out: [B,T,C] fp32.
// Block: 128 Q rows, 8 warps x 16 rows. KV 64-row tiles, cp.async 2-stage.
// Static smem: Ks[2][64*72] + Vs[2][64*72] bf16 = 36864 B.
#define KVW 72

__global__ __launch_bounds__(256, 2) void flash_bf(
    const __nv_bfloat16* __restrict__ Qg,
    const __nv_bfloat16* __restrict__ Kg,
    const __nv_bfloat16* __restrict__ Vg,
    float* __restrict__ Out,
    int causal)
{
    __shared__ __nv_bfloat16 Ks[2][64 * KVW];
    __shared__ __nv_bfloat16 Vs[2][64 * KVW];

    int bh = blockIdx.y;
    int b = bh >> 3, h = bh & 7;
    int q0 = blockIdx.x * 128;
    long base = (long)bh * T_ * HS_;
    const __nv_bfloat16* Qb = Qg + base;
    const __nv_bfloat16* Kb = Kg + base;
    const __nv_bfloat16* Vb = Vg + base;

    int tid = threadIdx.x;
    int lane = tid & 31, w = tid >> 5;
    int g = lane >> 2, t4 = lane & 3;
    int wr = w * 16;

    // KV tile load: per tensor 64 rows x 64 bf16 = 8192 B = 512 x 16B, 2/thread
    auto loadKV = [&](int st, int s0) {
        #pragma unroll
        for (int j = 0; j < 2; j++) {
            int c = tid + j * 256;
            int row = c >> 3;
            int cc = (c & 7) * 8;
            cp16(&Ks[st][row * KVW + cc], Kb + (long)(s0 + row) * HS_ + cc);
            cp16(&Vs[st][row * KVW + cc], Vb + (long)(s0 + row) * HS_ + cc);
        }
    };

    // Q fragments (bf16 pairs), held for the whole block: 4 k-chunks x 4 regs
    unsigned Qa[4][4];
    {
        const __nv_bfloat16* q0p = Qb + (long)(q0 + wr + g) * HS_;
        const __nv_bfloat16* q1p = q0p + 8 * HS_;
        #pragma unroll
        for (int c = 0; c < 4; c++) {
            Qa[c][0] = *reinterpret_cast<const unsigned*>(&q0p[c * 16 + 2 * t4]);
            Qa[c][1] = *reinterpret_cast<const unsigned*>(&q1p[c * 16 + 2 * t4]);
            Qa[c][2] = *reinterpret_cast<const unsigned*>(&q0p[c * 16 + 8 + 2 * t4]);
            Qa[c][3] = *reinterpret_cast<const unsigned*>(&q1p[c * 16 + 8 + 2 * t4]);
        }
    }

    float Oacc[8][4];
    #pragma unroll
    for (int i = 0; i < 8; i++)
        #pragma unroll
        for (int j = 0; j < 4; j++) Oacc[i][j] = 0.f;
    float m0 = -1e30f, m1 = -1e30f, l0 = 0.f, l1 = 0.f;

    int nT = causal ? (q0 / 64 + 2) : (T_ / 64);

    loadKV(0, 0);
    CP_COMMIT();

    // ldmatrix.trans per-thread fixed offsets (elements)
    int lmj = lane >> 3, lmt = lane & 7;
    int vt_off = ((lmj & 1) * 8 + lmt) * KVW + (lmj >> 1) * 8;

    for (int it = 0; it < nT; it++) {
        int s = it & 1;
        int s0 = it * 64;
        CP_WAIT(0);
        __syncthreads();
        if (it + 1 < nT) {
            loadKV(s ^ 1, (it + 1) * 64);
            CP_COMMIT();
        }

        const __nv_bfloat16* Kt = Ks[s];
        unsigned vbase = sm_u32(&Vs[s][0]);

        // S = (Q K^T) * 0.125
        float S[8][4];
        #pragma unroll
        for (int nf = 0; nf < 8; nf++)
            #pragma unroll
            for (int j = 0; j < 4; j++) S[nf][j] = 0.f;

        #pragma unroll
        for (int c = 0; c < 4; c++) {
            #pragma unroll
            for (int nf = 0; nf < 8; nf++) {
                const __nv_bfloat16* kr = &Kt[(nf * 8 + g) * KVW + c * 16 + 2 * t4];
                unsigned b0 = *reinterpret_cast<const unsigned*>(kr);
                unsigned b1 = *reinterpret_cast<const unsigned*>(kr + 8);
                mma_bf16(S[nf], Qa[c], b0, b1);
            }
        }
        #pragma unroll
        for (int nf = 0; nf < 8; nf++)
            #pragma unroll
            for (int j = 0; j < 4; j++) S[nf][j] *= 0.125f;

        // causal mask (diagonal tiles only)
        if (causal && (s0 + 63 > q0 + wr)) {
            int r0g = q0 + wr + g;
            #pragma unroll
            for (int nf = 0; nf < 8; nf++) {
                int cbase = s0 + nf * 8 + 2 * t4;
                if (cbase     > r0g)     S[nf][0] = -1e30f;
                if (cbase + 1 > r0g)     S[nf][1] = -1e30f;
                if (cbase     > r0g + 8) S[nf][2] = -1e30f;
                if (cbase + 1 > r0g + 8) S[nf][3] = -1e30f;
            }
        }

        // row max (reduce over t4 quad)
        float tm0 = -1e30f, tm1 = -1e30f;
        #pragma unroll
        for (int nf = 0; nf < 8; nf++) {
            tm0 = fmaxf(tm0, fmaxf(S[nf][0], S[nf][1]));
            tm1 = fmaxf(tm1, fmaxf(S[nf][2], S[nf][3]));
        }
        tm0 = fmaxf(tm0, __shfl_xor_sync(0xffffffffu, tm0, 1));
        tm0 = fmaxf(tm0, __shfl_xor_sync(0xffffffffu, tm0, 2));
        tm1 = fmaxf(tm1, __shfl_xor_sync(0xffffffffu, tm1, 1));
        tm1 = fmaxf(tm1, __shfl_xor_sync(0xffffffffu, tm1, 2));

        float nm0 = fmaxf(m0, tm0), nm1 = fmaxf(m1, tm1);
        float f0 = __expf(m0 - nm0), f1 = __expf(m1 - nm1);

        float rs0 = 0.f, rs1 = 0.f;
        #pragma unroll
        for (int nf = 0; nf < 8; nf++) {
            S[nf][0] = __expf(S[nf][0] - nm0);
            S[nf][1] = __expf(S[nf][1] - nm0);
            S[nf][2] = __expf(S[nf][2] - nm1);
            S[nf][3] = __expf(S[nf][3] - nm1);
            rs0 += S[nf][0] + S[nf][1];
            rs1 += S[nf][2] + S[nf][3];
        }
        rs0 += __shfl_xor_sync(0xffffffffu, rs0, 1);
        rs0 += __shfl_xor_sync(0xffffffffu, rs0, 2);
        rs1 += __shfl_xor_sync(0xffffffffu, rs1, 1);
        rs1 += __shfl_xor_sync(0xffffffffu, rs1, 2);

        l0 = l0 * f0 + rs0;
        l1 = l1 * f1 + rs1;
        m0 = nm0; m1 = nm1;

        #pragma unroll
        for (int nf = 0; nf < 8; nf++) {
            Oacc[nf][0] *= f0; Oacc[nf][1] *= f0;
            Oacc[nf][2] *= f1; Oacc[nf][3] *= f1;
        }

        // O += P V : A-frags are direct bf16x2 packs of S; B-frags via ldmatrix.trans
        #pragma unroll
        for (int c = 0; c < 4; c++) {
            unsigned a4[4];
            a4[0] = packbf(S[2 * c][0],     S[2 * c][1]);      // row g,   keys 16c+2t4
            a4[1] = packbf(S[2 * c][2],     S[2 * c][3]);      // row g+8
            a4[2] = packbf(S[2 * c + 1][0], S[2 * c + 1][1]);  // row g,   keys 16c+8+2t4
            a4[3] = packbf(S[2 * c + 1][2], S[2 * c + 1][3]);  // row g+8
            #pragma unroll
            for (int gi = 0; gi < 4; gi++) {
                unsigned r0, r1, r2, r3;
                unsigned addr = vbase + (unsigned)((c * 16 * KVW + gi * 16 + vt_off) * 2);
                asm volatile(
                    "ldmatrix.sync.aligned.m8n8.x4.trans.shared.b16 {%0,%1,%2,%3}, [%4];"
                    : "=r"(r0), "=r"(r1), "=r"(r2), "=r"(r3) : "r"(addr));
                mma_bf16(Oacc[2 * gi],     a4, r0, r1);
                mma_bf16(Oacc[2 * gi + 1], a4, r2, r3);
            }
        }
    }

    // epilogue: normalize and write [B,T,C]
    float inv0 = 1.f / l0, inv1 = 1.f / l1;
    float* o0 = Out + ((long)b * T_ + q0 + wr + g) * C_ + h * HS_;
    float* o1 = Out + ((long)b * T_ + q0 + wr + g + 8) * C_ + h * HS_;
    #pragma unroll
    for (int nf = 0; nf < 8; nf++) {
        int c = nf * 8 + 2 * t4;
        float2 v0 = {Oacc[nf][0] * inv0, Oacc[nf][1] * inv0};
        float2 v1 = {Oacc[nf][2] * inv1, Oacc[nf][3] * inv1};
        *reinterpret_cast<float2*>(o0 + c) = v0;
        *reinterpret_cast<float2*>(o1 + c) = v1;
    }
}

// ---------------- orchestration ----------------
extern "C" void kernel_launch(void* const* d_in, const int* in_sizes, int n_in,
                              void* d_out, int out_size)
{
    const float* hidden = (const float*)d_in[0];
    const float* target = (const float*)d_in[1];
    const float* Wq_s = (const float*)d_in[2];
    const float* Wk_s = (const float*)d_in[3];
    const float* Wv_s = (const float*)d_in[4];
    const float* Wo_s = (const float*)d_in[5];
    const float* bo_s = (const float*)d_in[6];
    const float* Wq_x = (const float*)d_in[7];
    const float* Wk_x = (const float*)d_in[8];
    const float* Wv_x = (const float*)d_in[9];
    const float* Wo_x = (const float*)d_in[10];
    const float* bo_x = (const float*)d_in[11];
    const float* W1 = (const float*)d_in[12];
    const float* b1 = (const float*)d_in[13];
    const float* W2 = (const float*)d_in[14];
    const float* b2 = (const float*)d_in[15];
    const float* g1 = (const float*)d_in[16];
    const float* g2 = (const float*)d_in[17];
    const float* g3 = (const float*)d_in[18];
    const float* g4 = (const float*)d_in[19];

    float* t = (float*)d_out;

    float *xnorm, *hnorm, *attn, *ff;
    __nv_bfloat16 *qb, *kb, *vb;
    cudaGetSymbolAddress((void**)&xnorm, g_xnorm);
    cudaGetSymbolAddress((void**)&hnorm, g_hnorm);
    cudaGetSymbolAddress((void**)&qb, g_q);
    cudaGetSymbolAddress((void**)&kb, g_k);
    cudaGetSymbolAddress((void**)&vb, g_v);
    cudaGetSymbolAddress((void**)&attn, g_attn);
    cudaGetSymbolAddress((void**)&ff, g_ff);

    copy_k<<<(BTC_ / 4 + 255) / 256, 256>>>((float4*)t, (const float4*)target, BTC_ / 4);

    const long HCHS = (long)H_ * C_ * HS_;   // per-layer weight stride
    const long CHS  = (long)C_ * HS_;        // per-head weight stride
    const long BHT  = (long)H_ * T_ * HS_;   // per-b stride of q/k/v (elements)

    dim3 gQKV(12, T_ / 128, NB);             // 3 projections x 4 col-blocks, z=b
    dim3 gO(C_ / 128, BT_ / 128, 1);
    dim3 gF1(FF_ / 128, BT_ / 128, 1);
    dim3 gF2(C_ / 128, BT_ / 128, 1);
    dim3 gFl(T_ / 128, BH_, 1);

    for (int l = 0; l < NL; l++) {
        // ======== masked self-attention ========
        rmsnorm_k<<<BT_, 256>>>(t, g1 + (long)l * C_, xnorm);

        gemm128<<<gQKV, 256>>>(C_,
            xnorm, C_, (long)T_ * C_,
            Wq_s + l * HCHS, Wk_s + l * HCHS, Wv_s + l * HCHS, 0, CHS, 1,
            nullptr,
            (float*)qb, (float*)kb, (float*)vb, 0, BHT, (long)T_ * HS_, 1,
            0, 0, 4, 1);

        flash_bf<<<gFl, 256>>>(qb, kb, vb, attn, 1);

        gemm128<<<gO, 256>>>(C_,
            attn, C_, 0,
            Wo_s + (long)l * C_ * C_, Wo_s + (long)l * C_ * C_, Wo_s + (long)l * C_ * C_,
            C_, 0, 0,
            bo_s + (long)l * C_,
            t, t, t, C_, 0, 0, 0,
            1, 0, C_ / 128, 0);

        // ======== cross-attention ========
        rmsnorm_k<<<BT_, 256>>>(hidden, g2 + (long)l * C_, hnorm);
        rmsnorm_k<<<BT_, 256>>>(t, g3 + (long)l * C_, xnorm);

        // Q from xnorm
        gemm128<<<dim3(4, T_ / 128, NB), 256>>>(C_,
            xnorm, C_, (long)T_ * C_,
            Wq_x + l * HCHS, Wq_x + l * HCHS, Wq_x + l * HCHS, 0, CHS, 1,
            nullptr,
            (float*)qb, (float*)qb, (float*)qb, 0, BHT, (long)T_ * HS_, 1,
            0, 0, 4, 1);
        // K,V from hnorm (fused pair)
        gemm128<<<dim3(8, T_ / 128, NB), 256>>>(C_,
            hnorm, C_, (long)T_ * C_,
            Wk_x + l * HCHS, Wv_x + l * HCHS, Wv_x + l * HCHS, 0, CHS, 1,
            nullptr,
            (float*)kb, (float*)vb, (float*)vb, 0, BHT, (long)T_ * HS_, 1,
            0, 0, 4, 1);

        flash_bf<<<gFl, 256>>>(qb, kb, vb, attn, 0);

        gemm128<<<gO, 256>>>(C_,
            attn, C_, 0,
            Wo_x + (long)l * C_ * C_, Wo_x + (long)l * C_ * C_, Wo_x + (long)l * C_ * C_,
            C_, 0, 0,
            bo_x + (long)l * C_,
            t, t, t, C_, 0, 0, 0,
            1, 0, C_ / 128, 0);

        // ======== GELU FFN ========
        rmsnorm_k<<<BT_, 256>>>(t, g4 + (long)l * C_, xnorm);

        gemm128<<<gF1, 256>>>(C_,
            xnorm, C_, 0,
            W1 + (long)l * C_ * FF_, W1 + (long)l * C_ * FF_, W1 + (long)l * C_ * FF_,
            FF_, 0, 0,
            b1 + (long)l * FF_,
            ff, ff, ff, FF_, 0, 0, 0,
            0, 1, FF_ / 128, 0);

        gemm128<<<gF2, 256>>>(FF_,
            ff, FF_, 0,
            W2 + (long)l * FF_ * C_, W2 + (long)l * FF_ * C_, W2 + (long)l * FF_ * C_,
            C_, 0, 0,
            b2 + (long)l * C_,
            t, t, t, C_, 0, 0, 0,
            1, 0, C_ / 128, 0);
    }
}

// round 9
// speedup vs baseline: 1.4917x; 1.1274x over previous
#include <cuda_runtime.h>
#include <cuda_bf16.h>
#include <math.h>

// Problem dims
#define NL  2
#define NB  2
#define T_  2048
#define C_  512
#define H_  8
#define FF_ 1024
#define HS_ 64
#define EPS_ 1.1920929e-07f

#define BT_  (NB * T_)        // 4096 rows
#define BTC_ (NB * T_ * C_)   // 2097152
#define BH_  (NB * H_)        // 16

// ---------------- scratch ----------------
__device__ float g_xnorm[BTC_];
__device__ __nv_bfloat16 g_xnb[BTC_];   // bf16 normed activations (attention path)
__device__ __nv_bfloat16 g_hnb[BTC_];
__device__ __nv_bfloat16 g_q[BTC_];     // [B,H,T,HS] bf16
__device__ __nv_bfloat16 g_k[BTC_];
__device__ __nv_bfloat16 g_v[BTC_];
__device__ float g_attn[BTC_];          // [B,T,C]
__device__ float g_ff[NB * T_ * FF_];

// ---------------- cp.async helpers ----------------
__device__ __forceinline__ unsigned sm_u32(const void* p) {
    return (unsigned)__cvta_generic_to_shared(p);
}
__device__ __forceinline__ void cp16(void* dst_smem, const void* src) {
    asm volatile("cp.async.cg.shared.global [%0], [%1], 16;"
                 :: "r"(sm_u32(dst_smem)), "l"(src));
}
#define CP_COMMIT() asm volatile("cp.async.commit_group;")
#define CP_WAIT(n)  asm volatile("cp.async.wait_group %0;" :: "n"(n))

// ---------------- helpers ----------------
__global__ void copy_k(float4* __restrict__ dst, const float4* __restrict__ src, int n4) {
    int i = blockIdx.x * blockDim.x + threadIdx.x;
    if (i < n4) dst[i] = src[i];
}

// rmsnorm; out_bf selects bf16 output (attention path) vs fp32 (FFN path).
__global__ __launch_bounds__(256) void rmsnorm_k(
    const float* __restrict__ x, const float* __restrict__ g,
    float* __restrict__ outf, __nv_bfloat16* __restrict__ outb, int out_bf)
{
    long row = blockIdx.x;
    const float* xr = x + row * C_;
    int tid = threadIdx.x;
    float v0 = xr[tid];
    float v1 = xr[tid + 256];
    float ss = v0 * v0 + v1 * v1;

    __shared__ float red[8];
    #pragma unroll
    for (int o = 16; o; o >>= 1) ss += __shfl_xor_sync(0xffffffffu, ss, o);
    if ((tid & 31) == 0) red[tid >> 5] = ss;
    __syncthreads();
    if (tid == 0) {
        float s = 0.f;
        #pragma unroll
        for (int w = 0; w < 8; w++) s += red[w];
        red[0] = rsqrtf(s * (1.0f / C_) + EPS_);
    }
    __syncthreads();
    float r = red[0];
    float o0 = v0 * r * g[tid];
    float o1 = v1 * r * g[tid + 256];
    if (out_bf) {
        __nv_bfloat16* ob = outb + row * C_;
        ob[tid]       = __float2bfloat16_rn(o0);
        ob[tid + 256] = __float2bfloat16_rn(o1);
    } else {
        float* of = outf + row * C_;
        of[tid]       = o0;
        of[tid + 256] = o1;
    }
}

// ---------------- mma helpers ----------------
__device__ __forceinline__ void mma_tf32(float* d, const unsigned* a, const unsigned* b) {
    asm volatile(
        "mma.sync.aligned.m16n8k8.row.col.f32.tf32.tf32.f32 "
        "{%0,%1,%2,%3}, {%4,%5,%6,%7}, {%8,%9}, {%0,%1,%2,%3};"
        : "+f"(d[0]), "+f"(d[1]), "+f"(d[2]), "+f"(d[3])
        : "r"(a[0]), "r"(a[1]), "r"(a[2]), "r"(a[3]), "r"(b[0]), "r"(b[1]));
}
__device__ __forceinline__ void mma_bf16(float* d, const unsigned* a, unsigned b0, unsigned b1) {
    asm volatile(
        "mma.sync.aligned.m16n8k16.row.col.f32.bf16.bf16.f32 "
        "{%0,%1,%2,%3}, {%4,%5,%6,%7}, {%8,%9}, {%0,%1,%2,%3};"
        : "+f"(d[0]), "+f"(d[1]), "+f"(d[2]), "+f"(d[3])
        : "r"(a[0]), "r"(a[1]), "r"(a[2]), "r"(a[3]), "r"(b0), "r"(b1));
}
__device__ __forceinline__ unsigned fbits(float x) { return __float_as_uint(x); }
__device__ __forceinline__ unsigned packbf(float lo, float hi) {
    unsigned d;
    asm("cvt.rn.bf16x2.f32 %0, %1, %2;" : "=r"(d) : "f"(hi), "f"(lo));
    return d;
}

// ---------------- bf16 QKV projection GEMM ----------------
// A: [NB][T_][C_] bf16 (normed activations). B: fp32 weights [H][C_][HS_] per sel.
// C: [NB][H][T_][HS_] bf16.  Tile 128x128, BK=32, 2-stage, ldmatrix + m16n8k16.
#define QASTR 40    // A smem row pitch (bf16 elems): 32 + 8 pad
#define QBSTR 136   // B smem row pitch (bf16 elems): 128 + 8 pad
__global__ __launch_bounds__(256) void gemm_qkv_bf(
    const __nv_bfloat16* __restrict__ A,
    const float* __restrict__ B0, const float* __restrict__ B1, const float* __restrict__ B2,
    __nv_bfloat16* __restrict__ C0, __nv_bfloat16* __restrict__ C1, __nv_bfloat16* __restrict__ C2,
    int nColBlk)
{
    __shared__ __nv_bfloat16 As[2][128 * QASTR];
    __shared__ __nv_bfloat16 Bs[2][32 * QBSTR];

    int sel  = blockIdx.x / nColBlk;
    int colb = blockIdx.x - sel * nColBlk;
    const float* B = (sel == 0) ? B0 : (sel == 1) ? B1 : B2;
    __nv_bfloat16* Cp = ((sel == 0) ? C0 : (sel == 1) ? C1 : C2)
                        + (long)blockIdx.z * H_ * T_ * HS_;

    const __nv_bfloat16* Ab = A + (long)blockIdx.z * T_ * C_ + (long)(blockIdx.y * 128) * C_;
    int col0 = colb * 128;

    int tid = threadIdx.x, lane = tid & 31, w = tid >> 5;
    int g = lane >> 2, t4 = lane & 3;
    int wm = w & 1, wn = w >> 1;   // 2x4 warp grid: 64 rows x 32 cols each

    float acc[4][4][4];
    #pragma unroll
    for (int i = 0; i < 4; i++)
        #pragma unroll
        for (int j = 0; j < 4; j++)
            #pragma unroll
            for (int q = 0; q < 4; q++) acc[i][j][q] = 0.f;

    // A cp.async: 128 rows x 32 bf16 = 512 x 16B chunks, 2/thread
    auto cpA = [&](int st, int k0) {
        #pragma unroll
        for (int j = 0; j < 2; j++) {
            int c = tid * 2 + j;
            int row = c >> 2, kc = (c & 3) * 8;
            cp16(&As[st][row * QASTR + kc], Ab + (long)row * C_ + k0 + kc);
        }
    };

    // B: fp32 LDG -> bf16 STS (register prefetch). thread: k=tid>>3, n0=(tid&7)*16
    int bk = tid >> 3;
    int bn0 = (tid & 7) * 16;
    float4 bp[4];
    auto ldB = [&](int k0) {
        #pragma unroll
        for (int jj = 0; jj < 4; jj++) {
            int gc = col0 + bn0 + jj * 4;
            bp[jj] = *reinterpret_cast<const float4*>(
                &B[(long)(gc >> 6) * C_ * HS_ + (long)(k0 + bk) * HS_ + (gc & 63)]);
        }
    };
    auto stB = [&](int st) {
        #pragma unroll
        for (int jj = 0; jj < 4; jj++) {
            uint2 u = { packbf(bp[jj].x, bp[jj].y), packbf(bp[jj].z, bp[jj].w) };
            *reinterpret_cast<uint2*>(&Bs[st][bk * QBSTR + bn0 + jj * 4]) = u;
        }
    };

    // ldmatrix lane offsets
    int a_lrow = lane & 15, a_lk = (lane >> 4) * 8;
    int b_lrow = ((lane >> 3) & 1) * 8 + (lane & 7), b_lc = (lane >> 4) * 8;

    cpA(0, 0); CP_COMMIT();
    ldB(0);

    #pragma unroll 1
    for (int kt = 0; kt < C_ / 32; kt++) {
        int s = kt & 1;
        CP_WAIT(0);
        stB(s);
        __syncthreads();
        if (kt + 1 < C_ / 32) {
            cpA(s ^ 1, (kt + 1) * 32);
            CP_COMMIT();
            ldB((kt + 1) * 32);
        }

        #pragma unroll
        for (int kc = 0; kc < 32; kc += 16) {
            unsigned afr[4][4];
            #pragma unroll
            for (int mi = 0; mi < 4; mi++) {
                int m0 = wm * 64 + mi * 16;
                unsigned addr = sm_u32(&As[s][(m0 + a_lrow) * QASTR + kc + a_lk]);
                asm volatile(
                    "ldmatrix.sync.aligned.m8n8.x4.shared.b16 {%0,%1,%2,%3}, [%4];"
                    : "=r"(afr[mi][0]), "=r"(afr[mi][1]), "=r"(afr[mi][2]), "=r"(afr[mi][3])
                    : "r"(addr));
            }
            #pragma unroll
            for (int gi = 0; gi < 2; gi++) {
                int n0 = wn * 32 + gi * 16;
                unsigned r0, r1, r2, r3;
                unsigned addr = sm_u32(&Bs[s][(kc + b_lrow) * QBSTR + n0 + b_lc]);
                asm volatile(
                    "ldmatrix.sync.aligned.m8n8.x4.trans.shared.b16 {%0,%1,%2,%3}, [%4];"
                    : "=r"(r0), "=r"(r1), "=r"(r2), "=r"(r3) : "r"(addr));
                #pragma unroll
                for (int mi = 0; mi < 4; mi++) {
                    mma_bf16(acc[mi][2 * gi],     afr[mi], r0, r1);
                    mma_bf16(acc[mi][2 * gi + 1], afr[mi], r2, r3);
                }
            }
        }
    }

    // epilogue: bf16, head-blocked [H][T][HS]
    int row0 = blockIdx.y * 128;
    #pragma unroll
    for (int mi = 0; mi < 4; mi++) {
        #pragma unroll
        for (int ni = 0; ni < 4; ni++) {
            int r0 = row0 + wm * 64 + mi * 16 + g;
            int c  = col0 + wn * 32 + ni * 8 + t4 * 2;
            long hb = (long)(c >> 6) * T_ * HS_ + (c & 63);
            #pragma unroll
            for (int half = 0; half < 2; half++) {
                int rr = r0 + half * 8;
                *reinterpret_cast<unsigned*>(&Cp[hb + (long)rr * HS_]) =
                    packbf(acc[mi][ni][half * 2 + 0], acc[mi][ni][half * 2 + 1]);
            }
        }
    }
}

// ---------------- dense GEMM (tf32): O-proj / FFN. 128x128, BK=16, cp.async 2-stage ----------------
#define ASTR 20
#define BSTR 136
__global__ __launch_bounds__(256) void gemm128(
    int K,
    const float* __restrict__ A, int lda,
    const float* __restrict__ B, int ldb,
    const float* __restrict__ bias,
    float* __restrict__ Cp, int ldc,
    int accumulate, int gelu_act)
{
    __shared__ float As[2][128 * ASTR];
    __shared__ float Bs[2][16 * BSTR];

    int row0 = blockIdx.y * 128;
    int col0 = blockIdx.x * 128;

    int tid = threadIdx.x;
    int lane = tid & 31, w = tid >> 5;
    int g = lane >> 2, t4 = lane & 3;
    int wm = w & 1, wn = w >> 1;

    float acc[4][4][4];
    #pragma unroll
    for (int i = 0; i < 4; i++)
        #pragma unroll
        for (int j = 0; j < 4; j++)
            #pragma unroll
            for (int q = 0; q < 4; q++) acc[i][j][q] = 0.f;

    const float* Abase = A + (long)row0 * lda;

    auto issue = [&](int st, int k0) {
        #pragma unroll
        for (int j = 0; j < 2; j++) {
            int c   = tid * 2 + j;
            int row = c >> 2;
            int kc  = (c & 3) * 4;
            cp16(&As[st][row * ASTR + kc], Abase + (long)row * lda + k0 + kc);
        }
        #pragma unroll
        for (int j = 0; j < 2; j++) {
            int c  = tid * 2 + j;
            int kk = c >> 5;
            int n4 = (c & 31) * 4;
            cp16(&Bs[st][kk * BSTR + n4], &B[(long)(k0 + kk) * ldb + col0 + n4]);
        }
    };

    int nK = K >> 4;
    issue(0, 0);
    CP_COMMIT();

    #pragma unroll 1
    for (int kt = 0; kt < nK; kt++) {
        int s = kt & 1;
        CP_WAIT(0);
        __syncthreads();
        if (kt + 1 < nK) {
            issue(s ^ 1, (kt + 1) * 16);
            CP_COMMIT();
        }

        #pragma unroll
        for (int kc = 0; kc < 16; kc += 8) {
            unsigned afr[4][4], bfr[4][2];
            #pragma unroll
            for (int mi = 0; mi < 4; mi++) {
                int m = wm * 64 + mi * 16 + g;
                afr[mi][0] = fbits(As[s][m * ASTR + kc + t4]);
                afr[mi][1] = fbits(As[s][(m + 8) * ASTR + kc + t4]);
                afr[mi][2] = fbits(As[s][m * ASTR + kc + t4 + 4]);
                afr[mi][3] = fbits(As[s][(m + 8) * ASTR + kc + t4 + 4]);
            }
            #pragma unroll
            for (int ni = 0; ni < 4; ni++) {
                int n = wn * 32 + ni * 8 + g;
                bfr[ni][0] = fbits(Bs[s][(kc + t4) * BSTR + n]);
                bfr[ni][1] = fbits(Bs[s][(kc + t4 + 4) * BSTR + n]);
            }
            #pragma unroll
            for (int mi = 0; mi < 4; mi++)
                #pragma unroll
                for (int ni = 0; ni < 4; ni++)
                    mma_tf32(acc[mi][ni], afr[mi], bfr[ni]);
        }
    }

    #pragma unroll
    for (int mi = 0; mi < 4; mi++) {
        #pragma unroll
        for (int ni = 0; ni < 4; ni++) {
            int r0 = row0 + wm * 64 + mi * 16 + g;
            int c  = col0 + wn * 32 + ni * 8 + t4 * 2;
            #pragma unroll
            for (int half = 0; half < 2; half++) {
                int rr = r0 + half * 8;
                float v0 = acc[mi][ni][half * 2 + 0];
                float v1 = acc[mi][ni][half * 2 + 1];
                if (bias) { v0 += bias[c]; v1 += bias[c + 1]; }
                if (gelu_act) {
                    v0 = 0.5f * v0 * (1.0f + erff(v0 * 0.70710678118654752f));
                    v1 = 0.5f * v1 * (1.0f + erff(v1 * 0.70710678118654752f));
                }
                float* crow = &Cp[(long)rr * ldc + c];
                if (accumulate) { crow[0] += v0; crow[1] += v1; }
                else            { crow[0]  = v0; crow[1]  = v1; }
            }
        }
    }
}

// ---------------- fused flash attention (bf16 mma m16n8k16, online softmax) ----------------
#define KVW 72

__global__ __launch_bounds__(256, 2) void flash_bf(
    const __nv_bfloat16* __restrict__ Qg,
    const __nv_bfloat16* __restrict__ Kg,
    const __nv_bfloat16* __restrict__ Vg,
    float* __restrict__ Out,
    int causal)
{
    __shared__ __nv_bfloat16 Ks[2][64 * KVW];
    __shared__ __nv_bfloat16 Vs[2][64 * KVW];

    int bh = blockIdx.y;
    int b = bh >> 3, h = bh & 7;
    int q0 = blockIdx.x * 128;
    long base = (long)bh * T_ * HS_;
    const __nv_bfloat16* Qb = Qg + base;
    const __nv_bfloat16* Kb = Kg + base;
    const __nv_bfloat16* Vb = Vg + base;

    int tid = threadIdx.x;
    int lane = tid & 31, w = tid >> 5;
    int g = lane >> 2, t4 = lane & 3;
    int wr = w * 16;

    auto loadKV = [&](int st, int s0) {
        #pragma unroll
        for (int j = 0; j < 2; j++) {
            int c = tid + j * 256;
            int row = c >> 3;
            int cc = (c & 7) * 8;
            cp16(&Ks[st][row * KVW + cc], Kb + (long)(s0 + row) * HS_ + cc);
            cp16(&Vs[st][row * KVW + cc], Vb + (long)(s0 + row) * HS_ + cc);
        }
    };

    unsigned Qa[4][4];
    {
        const __nv_bfloat16* q0p = Qb + (long)(q0 + wr + g) * HS_;
        const __nv_bfloat16* q1p = q0p + 8 * HS_;
        #pragma unroll
        for (int c = 0; c < 4; c++) {
            Qa[c][0] = *reinterpret_cast<const unsigned*>(&q0p[c * 16 + 2 * t4]);
            Qa[c][1] = *reinterpret_cast<const unsigned*>(&q1p[c * 16 + 2 * t4]);
            Qa[c][2] = *reinterpret_cast<const unsigned*>(&q0p[c * 16 + 8 + 2 * t4]);
            Qa[c][3] = *reinterpret_cast<const unsigned*>(&q1p[c * 16 + 8 + 2 * t4]);
        }
    }

    float Oacc[8][4];
    #pragma unroll
    for (int i = 0; i < 8; i++)
        #pragma unroll
        for (int j = 0; j < 4; j++) Oacc[i][j] = 0.f;
    float m0 = -1e30f, m1 = -1e30f, l0 = 0.f, l1 = 0.f;

    int nT = causal ? (q0 / 64 + 2) : (T_ / 64);

    loadKV(0, 0);
    CP_COMMIT();

    int lmj = lane >> 3, lmt = lane & 7;
    int vt_off = ((lmj & 1) * 8 + lmt) * KVW + (lmj >> 1) * 8;

    for (int it = 0; it < nT; it++) {
        int s = it & 1;
        int s0 = it * 64;
        CP_WAIT(0);
        __syncthreads();
        if (it + 1 < nT) {
            loadKV(s ^ 1, (it + 1) * 64);
            CP_COMMIT();
        }

        const __nv_bfloat16* Kt = Ks[s];
        unsigned vbase = sm_u32(&Vs[s][0]);

        float S[8][4];
        #pragma unroll
        for (int nf = 0; nf < 8; nf++)
            #pragma unroll
            for (int j = 0; j < 4; j++) S[nf][j] = 0.f;

        #pragma unroll
        for (int c = 0; c < 4; c++) {
            #pragma unroll
            for (int nf = 0; nf < 8; nf++) {
                const __nv_bfloat16* kr = &Kt[(nf * 8 + g) * KVW + c * 16 + 2 * t4];
                unsigned b0 = *reinterpret_cast<const unsigned*>(kr);
                unsigned b1 = *reinterpret_cast<const unsigned*>(kr + 8);
                mma_bf16(S[nf], Qa[c], b0, b1);
            }
        }
        #pragma unroll
        for (int nf = 0; nf < 8; nf++)
            #pragma unroll
            for (int j = 0; j < 4; j++) S[nf][j] *= 0.125f;

        if (causal && (s0 + 63 > q0 + wr)) {
            int r0g = q0 + wr + g;
            #pragma unroll
            for (int nf = 0; nf < 8; nf++) {
                int cbase = s0 + nf * 8 + 2 * t4;
                if (cbase     > r0g)     S[nf][0] = -1e30f;
                if (cbase + 1 > r0g)     S[nf][1] = -1e30f;
                if (cbase     > r0g + 8) S[nf][2] = -1e30f;
                if (cbase + 1 > r0g + 8) S[nf][3] = -1e30f;
            }
        }

        float tm0 = -1e30f, tm1 = -1e30f;
        #pragma unroll
        for (int nf = 0; nf < 8; nf++) {
            tm0 = fmaxf(tm0, fmaxf(S[nf][0], S[nf][1]));
            tm1 = fmaxf(tm1, fmaxf(S[nf][2], S[nf][3]));
        }
        tm0 = fmaxf(tm0, __shfl_xor_sync(0xffffffffu, tm0, 1));
        tm0 = fmaxf(tm0, __shfl_xor_sync(0xffffffffu, tm0, 2));
        tm1 = fmaxf(tm1, __shfl_xor_sync(0xffffffffu, tm1, 1));
        tm1 = fmaxf(tm1, __shfl_xor_sync(0xffffffffu, tm1, 2));

        float nm0 = fmaxf(m0, tm0), nm1 = fmaxf(m1, tm1);
        float f0 = __expf(m0 - nm0), f1 = __expf(m1 - nm1);

        float rs0 = 0.f, rs1 = 0.f;
        #pragma unroll
        for (int nf = 0; nf < 8; nf++) {
            S[nf][0] = __expf(S[nf][0] - nm0);
            S[nf][1] = __expf(S[nf][1] - nm0);
            S[nf][2] = __expf(S[nf][2] - nm1);
            S[nf][3] = __expf(S[nf][3] - nm1);
            rs0 += S[nf][0] + S[nf][1];
            rs1 += S[nf][2] + S[nf][3];
        }
        rs0 += __shfl_xor_sync(0xffffffffu, rs0, 1);
        rs0 += __shfl_xor_sync(0xffffffffu, rs0, 2);
        rs1 += __shfl_xor_sync(0xffffffffu, rs1, 1);
        rs1 += __shfl_xor_sync(0xffffffffu, rs1, 2);

        l0 = l0 * f0 + rs0;
        l1 = l1 * f1 + rs1;
        m0 = nm0; m1 = nm1;

        #pragma unroll
        for (int nf = 0; nf < 8; nf++) {
            Oacc[nf][0] *= f0; Oacc[nf][1] *= f0;
            Oacc[nf][2] *= f1; Oacc[nf][3] *= f1;
        }

        #pragma unroll
        for (int c = 0; c < 4; c++) {
            unsigned a4[4];
            a4[0] = packbf(S[2 * c][0],     S[2 * c][1]);
            a4[1] = packbf(S[2 * c][2],     S[2 * c][3]);
            a4[2] = packbf(S[2 * c + 1][0], S[2 * c + 1][1]);
            a4[3] = packbf(S[2 * c + 1][2], S[2 * c + 1][3]);
            #pragma unroll
            for (int gi = 0; gi < 4; gi++) {
                unsigned r0, r1, r2, r3;
                unsigned addr = vbase + (unsigned)((c * 16 * KVW + gi * 16 + vt_off) * 2);
                asm volatile(
                    "ldmatrix.sync.aligned.m8n8.x4.trans.shared.b16 {%0,%1,%2,%3}, [%4];"
                    : "=r"(r0), "=r"(r1), "=r"(r2), "=r"(r3) : "r"(addr));
                mma_bf16(Oacc[2 * gi],     a4, r0, r1);
                mma_bf16(Oacc[2 * gi + 1], a4, r2, r3);
            }
        }
    }

    float inv0 = 1.f / l0, inv1 = 1.f / l1;
    float* o0 = Out + ((long)b * T_ + q0 + wr + g) * C_ + h * HS_;
    float* o1 = Out + ((long)b * T_ + q0 + wr + g + 8) * C_ + h * HS_;
    #pragma unroll
    for (int nf = 0; nf < 8; nf++) {
        int c = nf * 8 + 2 * t4;
        float2 v0 = {Oacc[nf][0] * inv0, Oacc[nf][1] * inv0};
        float2 v1 = {Oacc[nf][2] * inv1, Oacc[nf][3] * inv1};
        *reinterpret_cast<float2*>(o0 + c) = v0;
        *reinterpret_cast<float2*>(o1 + c) = v1;
    }
}

// ---------------- orchestration ----------------
extern "C" void kernel_launch(void* const* d_in, const int* in_sizes, int n_in,
                              void* d_out, int out_size)
{
    const float* hidden = (const float*)d_in[0];
    const float* target = (const float*)d_in[1];
    const float* Wq_s = (const float*)d_in[2];
    const float* Wk_s = (const float*)d_in[3];
    const float* Wv_s = (const float*)d_in[4];
    const float* Wo_s = (const float*)d_in[5];
    const float* bo_s = (const float*)d_in[6];
    const float* Wq_x = (const float*)d_in[7];
    const float* Wk_x = (const float*)d_in[8];
    const float* Wv_x = (const float*)d_in[9];
    const float* Wo_x = (const float*)d_in[10];
    const float* bo_x = (const float*)d_in[11];
    const float* W1 = (const float*)d_in[12];
    const float* b1 = (const float*)d_in[13];
    const float* W2 = (const float*)d_in[14];
    const float* b2 = (const float*)d_in[15];
    const float* g1 = (const float*)d_in[16];
    const float* g2 = (const float*)d_in[17];
    const float* g3 = (const float*)d_in[18];
    const float* g4 = (const float*)d_in[19];

    float* t = (float*)d_out;

    float *xnorm, *attn, *ff;
    __nv_bfloat16 *xnb, *hnb, *qb, *kb, *vb;
    cudaGetSymbolAddress((void**)&xnorm, g_xnorm);
    cudaGetSymbolAddress((void**)&xnb, g_xnb);
    cudaGetSymbolAddress((void**)&hnb, g_hnb);
    cudaGetSymbolAddress((void**)&qb, g_q);
    cudaGetSymbolAddress((void**)&kb, g_k);
    cudaGetSymbolAddress((void**)&vb, g_v);
    cudaGetSymbolAddress((void**)&attn, g_attn);
    cudaGetSymbolAddress((void**)&ff, g_ff);

    copy_k<<<(BTC_ / 4 + 255) / 256, 256>>>((float4*)t, (const float4*)target, BTC_ / 4);

    const long HCHS = (long)H_ * C_ * HS_;   // per-layer weight stride

    dim3 gQKV(12, T_ / 128, NB);             // 3 projections x 4 col-blocks, z=b
    dim3 gQx(4, T_ / 128, NB);
    dim3 gKVx(8, T_ / 128, NB);
    dim3 gO(C_ / 128, BT_ / 128, 1);
    dim3 gF1(FF_ / 128, BT_ / 128, 1);
    dim3 gF2(C_ / 128, BT_ / 128, 1);
    dim3 gFl(T_ / 128, BH_, 1);

    for (int l = 0; l < NL; l++) {
        // ======== masked self-attention ========
        rmsnorm_k<<<BT_, 256>>>(t, g1 + (long)l * C_, nullptr, xnb, 1);

        gemm_qkv_bf<<<gQKV, 256>>>(xnb,
            Wq_s + l * HCHS, Wk_s + l * HCHS, Wv_s + l * HCHS,
            qb, kb, vb, 4);

        flash_bf<<<gFl, 256>>>(qb, kb, vb, attn, 1);

        gemm128<<<gO, 256>>>(C_,
            attn, C_,
            Wo_s + (long)l * C_ * C_, C_,
            bo_s + (long)l * C_,
            t, C_, 1, 0);

        // ======== cross-attention ========
        rmsnorm_k<<<BT_, 256>>>(hidden, g2 + (long)l * C_, nullptr, hnb, 1);
        rmsnorm_k<<<BT_, 256>>>(t, g3 + (long)l * C_, nullptr, xnb, 1);

        gemm_qkv_bf<<<gQx, 256>>>(xnb,
            Wq_x + l * HCHS, Wq_x + l * HCHS, Wq_x + l * HCHS,
            qb, qb, qb, 4);
        gemm_qkv_bf<<<gKVx, 256>>>(hnb,
            Wk_x + l * HCHS, Wv_x + l * HCHS, Wv_x + l * HCHS,
            kb, vb, vb, 4);

        flash_bf<<<gFl, 256>>>(qb, kb, vb, attn, 0);

        gemm128<<<gO, 256>>>(C_,
            attn, C_,
            Wo_x + (long)l * C_ * C_, C_,
            bo_x + (long)l * C_,
            t, C_, 1, 0);

        // ======== GELU FFN ========
        rmsnorm_k<<<BT_, 256>>>(t, g4 + (long)l * C_, xnorm, nullptr, 0);

        gemm128<<<gF1, 256>>>(C_,
            xnorm, C_,
            W1 + (long)l * C_ * FF_, FF_,
            b1 + (long)l * FF_,
            ff, FF_, 0, 1);

        gemm128<<<gF2, 256>>>(FF_,
            ff, FF_,
            W2 + (long)l * FF_ * C_, C_,
            b2 + (long)l * C_,
            t, C_, 1, 0);
    }
}

// round 10
// speedup vs baseline: 1.8162x; 1.2175x over previous
#include <cuda_runtime.h>
#include <cuda_bf16.h>
#include <math.h>

// Problem dims
#define NL  2
#define NB  2
#define T_  2048
#define C_  512
#define H_  8
#define FF_ 1024
#define HS_ 64
#define EPS_ 1.1920929e-07f

#define BT_  (NB * T_)        // 4096 rows
#define BTC_ (NB * T_ * C_)   // 2097152
#define BH_  (NB * H_)        // 16

// ---------------- scratch ----------------
__device__ __nv_bfloat16 g_xnb[BTC_];    // bf16 normed activations
__device__ __nv_bfloat16 g_hnb[BTC_];
__device__ __nv_bfloat16 g_q[BTC_];      // [B,H,T,HS] bf16
__device__ __nv_bfloat16 g_k[BTC_];
__device__ __nv_bfloat16 g_v[BTC_];
__device__ __nv_bfloat16 g_attnb[BTC_];  // [B,T,C] bf16 (flash out)
__device__ __nv_bfloat16 g_ffb[NB * T_ * FF_];

// ---------------- cp.async helpers ----------------
__device__ __forceinline__ unsigned sm_u32(const void* p) {
    return (unsigned)__cvta_generic_to_shared(p);
}
__device__ __forceinline__ void cp16(void* dst_smem, const void* src) {
    asm volatile("cp.async.cg.shared.global [%0], [%1], 16;"
                 :: "r"(sm_u32(dst_smem)), "l"(src));
}
#define CP_COMMIT() asm volatile("cp.async.commit_group;")
#define CP_WAIT(n)  asm volatile("cp.async.wait_group %0;" :: "n"(n))

// ---------------- helpers ----------------
__global__ void copy_k(float4* __restrict__ dst, const float4* __restrict__ src, int n4) {
    int i = blockIdx.x * blockDim.x + threadIdx.x;
    if (i < n4) dst[i] = src[i];
}

// rmsnorm -> bf16 output
__global__ __launch_bounds__(256) void rmsnorm_k(
    const float* __restrict__ x, const float* __restrict__ g,
    __nv_bfloat16* __restrict__ outb)
{
    long row = blockIdx.x;
    const float* xr = x + row * C_;
    int tid = threadIdx.x;
    float v0 = xr[tid];
    float v1 = xr[tid + 256];
    float ss = v0 * v0 + v1 * v1;

    __shared__ float red[8];
    #pragma unroll
    for (int o = 16; o; o >>= 1) ss += __shfl_xor_sync(0xffffffffu, ss, o);
    if ((tid & 31) == 0) red[tid >> 5] = ss;
    __syncthreads();
    if (tid == 0) {
        float s = 0.f;
        #pragma unroll
        for (int w = 0; w < 8; w++) s += red[w];
        red[0] = rsqrtf(s * (1.0f / C_) + EPS_);
    }
    __syncthreads();
    float r = red[0];
    __nv_bfloat16* ob = outb + row * C_;
    ob[tid]       = __float2bfloat16_rn(v0 * r * g[tid]);
    ob[tid + 256] = __float2bfloat16_rn(v1 * r * g[tid + 256]);
}

// ---------------- mma helpers ----------------
__device__ __forceinline__ void mma_bf16(float* d, const unsigned* a, unsigned b0, unsigned b1) {
    asm volatile(
        "mma.sync.aligned.m16n8k16.row.col.f32.bf16.bf16.f32 "
        "{%0,%1,%2,%3}, {%4,%5,%6,%7}, {%8,%9}, {%0,%1,%2,%3};"
        : "+f"(d[0]), "+f"(d[1]), "+f"(d[2]), "+f"(d[3])
        : "r"(a[0]), "r"(a[1]), "r"(a[2]), "r"(a[3]), "r"(b0), "r"(b1));
}
__device__ __forceinline__ unsigned packbf(float lo, float hi) {
    unsigned d;
    asm("cvt.rn.bf16x2.f32 %0, %1, %2;" : "=r"(d) : "f"(hi), "f"(lo));
    return d;
}
__device__ __forceinline__ float ex2f(float x) {
    float y;
    asm("ex2.approx.f32 %0, %1;" : "=f"(y) : "f"(x));
    return y;
}

#define QASTR 40    // A smem row pitch (bf16): 32 + 8 pad
#define QBSTR 136   // B smem row pitch (bf16): 128 + 8 pad

// ---------------- bf16 QKV projection GEMM (head-blocked B and C) ----------------
__global__ __launch_bounds__(256) void gemm_qkv_bf(
    const __nv_bfloat16* __restrict__ A,
    const float* __restrict__ B0, const float* __restrict__ B1, const float* __restrict__ B2,
    __nv_bfloat16* __restrict__ C0, __nv_bfloat16* __restrict__ C1, __nv_bfloat16* __restrict__ C2,
    int nColBlk)
{
    __shared__ __nv_bfloat16 As[2][128 * QASTR];
    __shared__ __nv_bfloat16 Bs[2][32 * QBSTR];

    int sel  = blockIdx.x / nColBlk;
    int colb = blockIdx.x - sel * nColBlk;
    const float* B = (sel == 0) ? B0 : (sel == 1) ? B1 : B2;
    __nv_bfloat16* Cp = ((sel == 0) ? C0 : (sel == 1) ? C1 : C2)
                        + (long)blockIdx.z * H_ * T_ * HS_;

    const __nv_bfloat16* Ab = A + (long)blockIdx.z * T_ * C_ + (long)(blockIdx.y * 128) * C_;
    int col0 = colb * 128;

    int tid = threadIdx.x, lane = tid & 31, w = tid >> 5;
    int g = lane >> 2, t4 = lane & 3;
    int wm = w & 1, wn = w >> 1;

    float acc[4][4][4];
    #pragma unroll
    for (int i = 0; i < 4; i++)
        #pragma unroll
        for (int j = 0; j < 4; j++)
            #pragma unroll
            for (int q = 0; q < 4; q++) acc[i][j][q] = 0.f;

    auto cpA = [&](int st, int k0) {
        #pragma unroll
        for (int j = 0; j < 2; j++) {
            int c = tid * 2 + j;
            int row = c >> 2, kc = (c & 3) * 8;
            cp16(&As[st][row * QASTR + kc], Ab + (long)row * C_ + k0 + kc);
        }
    };

    int bk = tid >> 3;
    int bn0 = (tid & 7) * 16;
    float4 bp[4];
    auto ldB = [&](int k0) {
        #pragma unroll
        for (int jj = 0; jj < 4; jj++) {
            int gc = col0 + bn0 + jj * 4;
            bp[jj] = *reinterpret_cast<const float4*>(
                &B[(long)(gc >> 6) * C_ * HS_ + (long)(k0 + bk) * HS_ + (gc & 63)]);
        }
    };
    auto stB = [&](int st) {
        #pragma unroll
        for (int jj = 0; jj < 4; jj++) {
            uint2 u = { packbf(bp[jj].x, bp[jj].y), packbf(bp[jj].z, bp[jj].w) };
            *reinterpret_cast<uint2*>(&Bs[st][bk * QBSTR + bn0 + jj * 4]) = u;
        }
    };

    int a_lrow = lane & 15, a_lk = (lane >> 4) * 8;
    int b_lrow = ((lane >> 3) & 1) * 8 + (lane & 7), b_lc = (lane >> 4) * 8;

    cpA(0, 0); CP_COMMIT();
    ldB(0);

    #pragma unroll 1
    for (int kt = 0; kt < C_ / 32; kt++) {
        int s = kt & 1;
        CP_WAIT(0);
        stB(s);
        __syncthreads();
        if (kt + 1 < C_ / 32) {
            cpA(s ^ 1, (kt + 1) * 32);
            CP_COMMIT();
            ldB((kt + 1) * 32);
        }

        #pragma unroll
        for (int kc = 0; kc < 32; kc += 16) {
            unsigned afr[4][4];
            #pragma unroll
            for (int mi = 0; mi < 4; mi++) {
                int m0 = wm * 64 + mi * 16;
                unsigned addr = sm_u32(&As[s][(m0 + a_lrow) * QASTR + kc + a_lk]);
                asm volatile(
                    "ldmatrix.sync.aligned.m8n8.x4.shared.b16 {%0,%1,%2,%3}, [%4];"
                    : "=r"(afr[mi][0]), "=r"(afr[mi][1]), "=r"(afr[mi][2]), "=r"(afr[mi][3])
                    : "r"(addr));
            }
            #pragma unroll
            for (int gi = 0; gi < 2; gi++) {
                int n0 = wn * 32 + gi * 16;
                unsigned r0, r1, r2, r3;
                unsigned addr = sm_u32(&Bs[s][(kc + b_lrow) * QBSTR + n0 + b_lc]);
                asm volatile(
                    "ldmatrix.sync.aligned.m8n8.x4.trans.shared.b16 {%0,%1,%2,%3}, [%4];"
                    : "=r"(r0), "=r"(r1), "=r"(r2), "=r"(r3) : "r"(addr));
                #pragma unroll
                for (int mi = 0; mi < 4; mi++) {
                    mma_bf16(acc[mi][2 * gi],     afr[mi], r0, r1);
                    mma_bf16(acc[mi][2 * gi + 1], afr[mi], r2, r3);
                }
            }
        }
    }

    int row0 = blockIdx.y * 128;
    #pragma unroll
    for (int mi = 0; mi < 4; mi++) {
        #pragma unroll
        for (int ni = 0; ni < 4; ni++) {
            int r0 = row0 + wm * 64 + mi * 16 + g;
            int c  = col0 + wn * 32 + ni * 8 + t4 * 2;
            long hb = (long)(c >> 6) * T_ * HS_ + (c & 63);
            #pragma unroll
            for (int half = 0; half < 2; half++) {
                int rr = r0 + half * 8;
                *reinterpret_cast<unsigned*>(&Cp[hb + (long)rr * HS_]) =
                    packbf(acc[mi][ni][half * 2 + 0], acc[mi][ni][half * 2 + 1]);
            }
        }
    }
}

// ---------------- bf16 dense GEMM (plain layouts): O-proj / FFN ----------------
// A bf16 [M,K] row-major. B fp32 [K,N] row-major (cvt to bf16 at stage).
// accumulate -> Cf fp32 +=, else Cb bf16 store (with optional gelu).
__global__ __launch_bounds__(256) void gemm_bf(
    int K,
    const __nv_bfloat16* __restrict__ A, int lda,
    const float* __restrict__ B, int ldb,
    const float* __restrict__ bias,
    float* __restrict__ Cf, __nv_bfloat16* __restrict__ Cb,
    int ldc, int accumulate, int gelu_act)
{
    __shared__ __nv_bfloat16 As[2][128 * QASTR];
    __shared__ __nv_bfloat16 Bs[2][32 * QBSTR];

    int row0 = blockIdx.y * 128;
    int col0 = blockIdx.x * 128;

    int tid = threadIdx.x, lane = tid & 31, w = tid >> 5;
    int g = lane >> 2, t4 = lane & 3;
    int wm = w & 1, wn = w >> 1;

    float acc[4][4][4];
    #pragma unroll
    for (int i = 0; i < 4; i++)
        #pragma unroll
        for (int j = 0; j < 4; j++)
            #pragma unroll
            for (int q = 0; q < 4; q++) acc[i][j][q] = 0.f;

    const __nv_bfloat16* Ab = A + (long)row0 * lda;

    auto cpA = [&](int st, int k0) {
        #pragma unroll
        for (int j = 0; j < 2; j++) {
            int c = tid * 2 + j;
            int row = c >> 2, kc = (c & 3) * 8;
            cp16(&As[st][row * QASTR + kc], Ab + (long)row * lda + k0 + kc);
        }
    };

    int bk = tid >> 3;
    int bn0 = (tid & 7) * 16;
    float4 bp[4];
    auto ldB = [&](int k0) {
        #pragma unroll
        for (int jj = 0; jj < 4; jj++)
            bp[jj] = *reinterpret_cast<const float4*>(
                &B[(long)(k0 + bk) * ldb + col0 + bn0 + jj * 4]);
    };
    auto stB = [&](int st) {
        #pragma unroll
        for (int jj = 0; jj < 4; jj++) {
            uint2 u = { packbf(bp[jj].x, bp[jj].y), packbf(bp[jj].z, bp[jj].w) };
            *reinterpret_cast<uint2*>(&Bs[st][bk * QBSTR + bn0 + jj * 4]) = u;
        }
    };

    int a_lrow = lane & 15, a_lk = (lane >> 4) * 8;
    int b_lrow = ((lane >> 3) & 1) * 8 + (lane & 7), b_lc = (lane >> 4) * 8;

    cpA(0, 0); CP_COMMIT();
    ldB(0);

    int nK = K / 32;
    #pragma unroll 1
    for (int kt = 0; kt < nK; kt++) {
        int s = kt & 1;
        CP_WAIT(0);
        stB(s);
        __syncthreads();
        if (kt + 1 < nK) {
            cpA(s ^ 1, (kt + 1) * 32);
            CP_COMMIT();
            ldB((kt + 1) * 32);
        }

        #pragma unroll
        for (int kc = 0; kc < 32; kc += 16) {
            unsigned afr[4][4];
            #pragma unroll
            for (int mi = 0; mi < 4; mi++) {
                int m0 = wm * 64 + mi * 16;
                unsigned addr = sm_u32(&As[s][(m0 + a_lrow) * QASTR + kc + a_lk]);
                asm volatile(
                    "ldmatrix.sync.aligned.m8n8.x4.shared.b16 {%0,%1,%2,%3}, [%4];"
                    : "=r"(afr[mi][0]), "=r"(afr[mi][1]), "=r"(afr[mi][2]), "=r"(afr[mi][3])
                    : "r"(addr));
            }
            #pragma unroll
            for (int gi = 0; gi < 2; gi++) {
                int n0 = wn * 32 + gi * 16;
                unsigned r0, r1, r2, r3;
                unsigned addr = sm_u32(&Bs[s][(kc + b_lrow) * QBSTR + n0 + b_lc]);
                asm volatile(
                    "ldmatrix.sync.aligned.m8n8.x4.trans.shared.b16 {%0,%1,%2,%3}, [%4];"
                    : "=r"(r0), "=r"(r1), "=r"(r2), "=r"(r3) : "r"(addr));
                #pragma unroll
                for (int mi = 0; mi < 4; mi++) {
                    mma_bf16(acc[mi][2 * gi],     afr[mi], r0, r1);
                    mma_bf16(acc[mi][2 * gi + 1], afr[mi], r2, r3);
                }
            }
        }
    }

    #pragma unroll
    for (int mi = 0; mi < 4; mi++) {
        #pragma unroll
        for (int ni = 0; ni < 4; ni++) {
            int r0 = row0 + wm * 64 + mi * 16 + g;
            int c  = col0 + wn * 32 + ni * 8 + t4 * 2;
            #pragma unroll
            for (int half = 0; half < 2; half++) {
                int rr = r0 + half * 8;
                float v0 = acc[mi][ni][half * 2 + 0];
                float v1 = acc[mi][ni][half * 2 + 1];
                if (bias) { v0 += bias[c]; v1 += bias[c + 1]; }
                if (gelu_act) {
                    v0 = 0.5f * v0 * (1.0f + erff(v0 * 0.70710678118654752f));
                    v1 = 0.5f * v1 * (1.0f + erff(v1 * 0.70710678118654752f));
                }
                if (accumulate) {
                    float* crow = &Cf[(long)rr * ldc + c];
                    crow[0] += v0; crow[1] += v1;
                } else {
                    *reinterpret_cast<unsigned*>(&Cb[(long)rr * ldc + c]) = packbf(v0, v1);
                }
            }
        }
    }
}

// ---------------- fused flash attention (bf16 mma, ldmatrix frags, exp2 softmax) ----------------
#define KVW 72
#define CEXP 0.18033688011112042f   // 0.125 * log2(e)

__global__ __launch_bounds__(256, 2) void flash_bf(
    const __nv_bfloat16* __restrict__ Qg,
    const __nv_bfloat16* __restrict__ Kg,
    const __nv_bfloat16* __restrict__ Vg,
    __nv_bfloat16* __restrict__ Out,
    int causal)
{
    __shared__ __nv_bfloat16 Ks[2][64 * KVW];
    __shared__ __nv_bfloat16 Vs[2][64 * KVW];

    int bh = blockIdx.y;
    int b = bh >> 3, h = bh & 7;
    int q0 = blockIdx.x * 128;
    long base = (long)bh * T_ * HS_;
    const __nv_bfloat16* Qb = Qg + base;
    const __nv_bfloat16* Kb = Kg + base;
    const __nv_bfloat16* Vb = Vg + base;

    int tid = threadIdx.x;
    int lane = tid & 31, w = tid >> 5;
    int g = lane >> 2, t4 = lane & 3;
    int wr = w * 16;

    auto loadKV = [&](int st, int s0) {
        #pragma unroll
        for (int j = 0; j < 2; j++) {
            int c = tid + j * 256;
            int row = c >> 3;
            int cc = (c & 7) * 8;
            cp16(&Ks[st][row * KVW + cc], Kb + (long)(s0 + row) * HS_ + cc);
            cp16(&Vs[st][row * KVW + cc], Vb + (long)(s0 + row) * HS_ + cc);
        }
    };

    unsigned Qa[4][4];
    {
        const __nv_bfloat16* q0p = Qb + (long)(q0 + wr + g) * HS_;
        const __nv_bfloat16* q1p = q0p + 8 * HS_;
        #pragma unroll
        for (int c = 0; c < 4; c++) {
            Qa[c][0] = *reinterpret_cast<const unsigned*>(&q0p[c * 16 + 2 * t4]);
            Qa[c][1] = *reinterpret_cast<const unsigned*>(&q1p[c * 16 + 2 * t4]);
            Qa[c][2] = *reinterpret_cast<const unsigned*>(&q0p[c * 16 + 8 + 2 * t4]);
            Qa[c][3] = *reinterpret_cast<const unsigned*>(&q1p[c * 16 + 8 + 2 * t4]);
        }
    }

    float Oacc[8][4];
    #pragma unroll
    for (int i = 0; i < 8; i++)
        #pragma unroll
        for (int j = 0; j < 4; j++) Oacc[i][j] = 0.f;
    // m tracked in RAW S units (pre-0.125 scale)
    float m0 = -1e30f, m1 = -1e30f, l0 = 0.f, l1 = 0.f;

    int nT = causal ? (q0 / 64 + 2) : (T_ / 64);

    loadKV(0, 0);
    CP_COMMIT();

    // ldmatrix per-thread offsets
    int lmj = lane >> 3, lmt = lane & 7;
    int vt_off = ((lmj & 1) * 8 + lmt) * KVW + (lmj >> 1) * 8;          // V (trans)
    int kt_row = (lane & 7) + 8 * (lane >> 4);                          // K (non-trans)
    int kt_add = ((lane >> 3) & 1) * 8;

    for (int it = 0; it < nT; it++) {
        int s = it & 1;
        int s0 = it * 64;
        CP_WAIT(0);
        __syncthreads();
        if (it + 1 < nT) {
            loadKV(s ^ 1, (it + 1) * 64);
            CP_COMMIT();
        }

        unsigned kbase = sm_u32(&Ks[s][0]);
        unsigned vbase = sm_u32(&Vs[s][0]);

        // S = Q K^T (raw; scale folded into exp2)
        float S[8][4];
        #pragma unroll
        for (int nf = 0; nf < 8; nf++)
            #pragma unroll
            for (int j = 0; j < 4; j++) S[nf][j] = 0.f;

        #pragma unroll
        for (int c = 0; c < 4; c++) {
            #pragma unroll
            for (int nfp = 0; nfp < 4; nfp++) {
                unsigned r0, r1, r2, r3;
                unsigned addr = kbase + (unsigned)(((nfp * 16 + kt_row) * KVW + c * 16 + kt_add) * 2);
                asm volatile(
                    "ldmatrix.sync.aligned.m8n8.x4.shared.b16 {%0,%1,%2,%3}, [%4];"
                    : "=r"(r0), "=r"(r1), "=r"(r2), "=r"(r3) : "r"(addr));
                mma_bf16(S[2 * nfp],     Qa[c], r0, r1);
                mma_bf16(S[2 * nfp + 1], Qa[c], r2, r3);
            }
        }

        // causal mask (diagonal tiles only)
        if (causal && (s0 + 63 > q0 + wr)) {
            int r0g = q0 + wr + g;
            #pragma unroll
            for (int nf = 0; nf < 8; nf++) {
                int cbase = s0 + nf * 8 + 2 * t4;
                if (cbase     > r0g)     S[nf][0] = -1e30f;
                if (cbase + 1 > r0g)     S[nf][1] = -1e30f;
                if (cbase     > r0g + 8) S[nf][2] = -1e30f;
                if (cbase + 1 > r0g + 8) S[nf][3] = -1e30f;
            }
        }

        // row max (raw units), reduce over t4 quad
        float tm0 = -1e30f, tm1 = -1e30f;
        #pragma unroll
        for (int nf = 0; nf < 8; nf++) {
            tm0 = fmaxf(tm0, fmaxf(S[nf][0], S[nf][1]));
            tm1 = fmaxf(tm1, fmaxf(S[nf][2], S[nf][3]));
        }
        tm0 = fmaxf(tm0, __shfl_xor_sync(0xffffffffu, tm0, 1));
        tm0 = fmaxf(tm0, __shfl_xor_sync(0xffffffffu, tm0, 2));
        tm1 = fmaxf(tm1, __shfl_xor_sync(0xffffffffu, tm1, 1));
        tm1 = fmaxf(tm1, __shfl_xor_sync(0xffffffffu, tm1, 2));

        float nm0 = fmaxf(m0, tm0), nm1 = fmaxf(m1, tm1);
        float f0 = ex2f((m0 - nm0) * CEXP), f1 = ex2f((m1 - nm1) * CEXP);

        float rs0 = 0.f, rs1 = 0.f;
        #pragma unroll
        for (int nf = 0; nf < 8; nf++) {
            S[nf][0] = ex2f((S[nf][0] - nm0) * CEXP);
            S[nf][1] = ex2f((S[nf][1] - nm0) * CEXP);
            S[nf][2] = ex2f((S[nf][2] - nm1) * CEXP);
            S[nf][3] = ex2f((S[nf][3] - nm1) * CEXP);
            rs0 += S[nf][0] + S[nf][1];
            rs1 += S[nf][2] + S[nf][3];
        }
        rs0 += __shfl_xor_sync(0xffffffffu, rs0, 1);
        rs0 += __shfl_xor_sync(0xffffffffu, rs0, 2);
        rs1 += __shfl_xor_sync(0xffffffffu, rs1, 1);
        rs1 += __shfl_xor_sync(0xffffffffu, rs1, 2);

        l0 = l0 * f0 + rs0;
        l1 = l1 * f1 + rs1;
        m0 = nm0; m1 = nm1;

        #pragma unroll
        for (int nf = 0; nf < 8; nf++) {
            Oacc[nf][0] *= f0; Oacc[nf][1] *= f0;
            Oacc[nf][2] *= f1; Oacc[nf][3] *= f1;
        }

        // O += P V : A-frags packed from S; B-frags via ldmatrix.trans
        #pragma unroll
        for (int c = 0; c < 4; c++) {
            unsigned a4[4];
            a4[0] = packbf(S[2 * c][0],     S[2 * c][1]);
            a4[1] = packbf(S[2 * c][2],     S[2 * c][3]);
            a4[2] = packbf(S[2 * c + 1][0], S[2 * c + 1][1]);
            a4[3] = packbf(S[2 * c + 1][2], S[2 * c + 1][3]);
            #pragma unroll
            for (int gi = 0; gi < 4; gi++) {
                unsigned r0, r1, r2, r3;
                unsigned addr = vbase + (unsigned)((c * 16 * KVW + gi * 16 + vt_off) * 2);
                asm volatile(
                    "ldmatrix.sync.aligned.m8n8.x4.trans.shared.b16 {%0,%1,%2,%3}, [%4];"
                    : "=r"(r0), "=r"(r1), "=r"(r2), "=r"(r3) : "r"(addr));
                mma_bf16(Oacc[2 * gi],     a4, r0, r1);
                mma_bf16(Oacc[2 * gi + 1], a4, r2, r3);
            }
        }
    }

    // epilogue: normalize and write bf16 [B,T,C]
    float inv0 = 1.f / l0, inv1 = 1.f / l1;
    __nv_bfloat16* o0 = Out + ((long)b * T_ + q0 + wr + g) * C_ + h * HS_;
    __nv_bfloat16* o1 = Out + ((long)b * T_ + q0 + wr + g + 8) * C_ + h * HS_;
    #pragma unroll
    for (int nf = 0; nf < 8; nf++) {
        int c = nf * 8 + 2 * t4;
        *reinterpret_cast<unsigned*>(&o0[c]) = packbf(Oacc[nf][0] * inv0, Oacc[nf][1] * inv0);
        *reinterpret_cast<unsigned*>(&o1[c]) = packbf(Oacc[nf][2] * inv1, Oacc[nf][3] * inv1);
    }
}

// ---------------- orchestration ----------------
extern "C" void kernel_launch(void* const* d_in, const int* in_sizes, int n_in,
                              void* d_out, int out_size)
{
    const float* hidden = (const float*)d_in[0];
    const float* target = (const float*)d_in[1];
    const float* Wq_s = (const float*)d_in[2];
    const float* Wk_s = (const float*)d_in[3];
    const float* Wv_s = (const float*)d_in[4];
    const float* Wo_s = (const float*)d_in[5];
    const float* bo_s = (const float*)d_in[6];
    const float* Wq_x = (const float*)d_in[7];
    const float* Wk_x = (const float*)d_in[8];
    const float* Wv_x = (const float*)d_in[9];
    const float* Wo_x = (const float*)d_in[10];
    const float* bo_x = (const float*)d_in[11];
    const float* W1 = (const float*)d_in[12];
    const float* b1 = (const float*)d_in[13];
    const float* W2 = (const float*)d_in[14];
    const float* b2 = (const float*)d_in[15];
    const float* g1 = (const float*)d_in[16];
    const float* g2 = (const float*)d_in[17];
    const float* g3 = (const float*)d_in[18];
    const float* g4 = (const float*)d_in[19];

    float* t = (float*)d_out;

    __nv_bfloat16 *xnb, *hnb, *qb, *kb, *vb, *attnb, *ffb;
    cudaGetSymbolAddress((void**)&xnb, g_xnb);
    cudaGetSymbolAddress((void**)&hnb, g_hnb);
    cudaGetSymbolAddress((void**)&qb, g_q);
    cudaGetSymbolAddress((void**)&kb, g_k);
    cudaGetSymbolAddress((void**)&vb, g_v);
    cudaGetSymbolAddress((void**)&attnb, g_attnb);
    cudaGetSymbolAddress((void**)&ffb, g_ffb);

    copy_k<<<(BTC_ / 4 + 255) / 256, 256>>>((float4*)t, (const float4*)target, BTC_ / 4);

    const long HCHS = (long)H_ * C_ * HS_;   // per-layer weight stride

    dim3 gQKV(12, T_ / 128, NB);
    dim3 gQx(4, T_ / 128, NB);
    dim3 gKVx(8, T_ / 128, NB);
    dim3 gO(C_ / 128, BT_ / 128, 1);
    dim3 gF1(FF_ / 128, BT_ / 128, 1);
    dim3 gF2(C_ / 128, BT_ / 128, 1);
    dim3 gFl(T_ / 128, BH_, 1);

    for (int l = 0; l < NL; l++) {
        // ======== masked self-attention ========
        rmsnorm_k<<<BT_, 256>>>(t, g1 + (long)l * C_, xnb);

        gemm_qkv_bf<<<gQKV, 256>>>(xnb,
            Wq_s + l * HCHS, Wk_s + l * HCHS, Wv_s + l * HCHS,
            qb, kb, vb, 4);

        flash_bf<<<gFl, 256>>>(qb, kb, vb, attnb, 1);

        gemm_bf<<<gO, 256>>>(C_,
            attnb, C_,
            Wo_s + (long)l * C_ * C_, C_,
            bo_s + (long)l * C_,
            t, nullptr, C_, 1, 0);

        // ======== cross-attention ========
        rmsnorm_k<<<BT_, 256>>>(hidden, g2 + (long)l * C_, hnb);
        rmsnorm_k<<<BT_, 256>>>(t, g3 + (long)l * C_, xnb);

        gemm_qkv_bf<<<gQx, 256>>>(xnb,
            Wq_x + l * HCHS, Wq_x + l * HCHS, Wq_x + l * HCHS,
            qb, qb, qb, 4);
        gemm_qkv_bf<<<gKVx, 256>>>(hnb,
            Wk_x + l * HCHS, Wv_x + l * HCHS, Wv_x + l * HCHS,
            kb, vb, vb, 4);

        flash_bf<<<gFl, 256>>>(qb, kb, vb, attnb, 0);

        gemm_bf<<<gO, 256>>>(C_,
            attnb, C_,
            Wo_x + (long)l * C_ * C_, C_,
            bo_x + (long)l * C_,
            t, nullptr, C_, 1, 0);

        // ======== GELU FFN ========
        rmsnorm_k<<<BT_, 256>>>(t, g4 + (long)l * C_, xnb);

        gemm_bf<<<gF1, 256>>>(C_,
            xnb, C_,
            W1 + (long)l * C_ * FF_, FF_,
            b1 + (long)l * FF_,
            nullptr, ffb, FF_, 0, 1);

        gemm_bf<<<gF2, 256>>>(FF_,
            ffb, FF_,
            W2 + (long)l * FF_ * C_, C_,
            b2 + (long)l * C_,
            t, nullptr, C_, 1, 0);
    }
}